// round 4
// baseline (speedup 1.0000x reference)
#include <cuda_runtime.h>
#include <cstdint>

#define S_LEN 2048
#define DM    1024
#define NH    16
#define HD    64
#define BATCH 2
#define M_TOT (BATCH * S_LEN)   // 4096

// ---------------- scratch (device globals: no allocation allowed) ----------
__device__ float g_Q[M_TOT * DM];
__device__ float g_K[M_TOT * DM];
__device__ float g_V[M_TOT * DM];
__device__ float g_O[M_TOT * DM];
__device__ float g_pad[BATCH * S_LEN];   // 1.0f = padded (id==0), 0.0f = valid

// ---------------------------------------------------------------------------
__device__ __forceinline__ uint32_t f2tf(float f) {
    uint32_t u;
    asm("cvt.rna.tf32.f32 %0, %1;" : "=r"(u) : "f"(f));
    return u;
}

__device__ __forceinline__ void mma8(float* c, const uint32_t* a, const uint32_t* b) {
    asm volatile(
        "mma.sync.aligned.m16n8k8.row.col.f32.tf32.tf32.f32 "
        "{%0,%1,%2,%3},{%4,%5,%6,%7},{%8,%9},{%0,%1,%2,%3};"
        : "+f"(c[0]), "+f"(c[1]), "+f"(c[2]), "+f"(c[3])
        : "r"(a[0]), "r"(a[1]), "r"(a[2]), "r"(a[3]), "r"(b[0]), "r"(b[1]));
}

// ---------------------------------------------------------------------------
// Pad-flag kernel with int32/int64 dtype sniffing (see R0 notes).
// ---------------------------------------------------------------------------
__global__ void pad_kernel(const int* __restrict__ ids)
{
    __shared__ int orv;
    if (threadIdx.x == 0) orv = 0;
    __syncthreads();
    int local = 0;
    for (int i = threadIdx.x; i < 2048; i += blockDim.x)
        local |= ids[2 * i + 1];
    atomicOr(&orv, local);
    __syncthreads();
    bool is64 = (orv == 0);
    for (int i = threadIdx.x; i < BATCH * S_LEN; i += blockDim.x) {
        int nz = is64 ? ((ids[2 * i] | ids[2 * i + 1]) != 0) : (ids[i] != 0);
        g_pad[i] = nz ? 0.0f : 1.0f;
    }
}

// ---------------------------------------------------------------------------
// TF32 tensor-core GEMM (NT), double-buffered smem.
// C[m][n] = sum_k A[m][k]*W[n][k] + bias[n]
// 128x128 tile, BK=16 x 2 stages, 8 warps (64x32 warp tiles), m16n8k8.
// ---------------------------------------------------------------------------
__global__ __launch_bounds__(256, 2)
void gemm_tf32(const float* __restrict__ A, const float* __restrict__ W,
               const float* __restrict__ bias, float* __restrict__ C,
               int M, int N, int K)
{
    __shared__ uint32_t As[2][16][136];   // [stage][k][m], bank = 8k+m
    __shared__ uint32_t Bs[2][16][136];

    const int tid  = threadIdx.x;
    const int lane = tid & 31;
    const int wid  = tid >> 5;
    const int g    = lane >> 2;   // 0..7
    const int t    = lane & 3;    // 0..3
    const int warp_m = wid & 1;   // 0..1 (64 rows each)
    const int warp_n = wid >> 1;  // 0..3 (32 cols each)

    const int row0 = blockIdx.y * 128;
    const int col0 = blockIdx.x * 128;

    int lr[2], lkq[2];
#pragma unroll
    for (int it = 0; it < 2; it++) {
        int linear = it * 256 + tid;
        lr[it]  = (linear & 31) | ((linear >> 7) << 5);
        lkq[it] = ((linear >> 5) & 3) * 4;
    }
    const float* Ap[2] = { A + (size_t)(row0 + lr[0]) * K + lkq[0],
                           A + (size_t)(row0 + lr[1]) * K + lkq[1] };
    const float* Wp[2] = { W + (size_t)(col0 + lr[0]) * K + lkq[0],
                           W + (size_t)(col0 + lr[1]) * K + lkq[1] };

    float c[4][4][4];
#pragma unroll
    for (int i = 0; i < 4; i++)
#pragma unroll
        for (int j = 0; j < 4; j++)
#pragma unroll
            for (int q = 0; q < 4; q++) c[i][j][q] = 0.0f;

    // prologue: fill stage 0
    {
        float4 pa[2], pb[2];
#pragma unroll
        for (int it = 0; it < 2; it++) {
            pa[it] = *(const float4*)(Ap[it]);
            pb[it] = *(const float4*)(Wp[it]);
        }
#pragma unroll
        for (int it = 0; it < 2; it++) {
            As[0][lkq[it] + 0][lr[it]] = f2tf(pa[it].x);
            As[0][lkq[it] + 1][lr[it]] = f2tf(pa[it].y);
            As[0][lkq[it] + 2][lr[it]] = f2tf(pa[it].z);
            As[0][lkq[it] + 3][lr[it]] = f2tf(pa[it].w);
            Bs[0][lkq[it] + 0][lr[it]] = f2tf(pb[it].x);
            Bs[0][lkq[it] + 1][lr[it]] = f2tf(pb[it].y);
            Bs[0][lkq[it] + 2][lr[it]] = f2tf(pb[it].z);
            Bs[0][lkq[it] + 3][lr[it]] = f2tf(pb[it].w);
        }
    }
    __syncthreads();

#pragma unroll 2
    for (int k0 = 0; k0 < K; k0 += 16) {
        const int buf = (k0 >> 4) & 1;
        const bool has_next = (k0 + 16) < K;

        // issue prefetch for next stage early
        float4 pa[2], pb[2];
        if (has_next) {
#pragma unroll
            for (int it = 0; it < 2; it++) {
                pa[it] = *(const float4*)(Ap[it] + k0 + 16);
                pb[it] = *(const float4*)(Wp[it] + k0 + 16);
            }
        }

        // compute on current stage
#pragma unroll
        for (int ks = 0; ks < 16; ks += 8) {
            uint32_t af[4][4], bf[4][2];
#pragma unroll
            for (int i = 0; i < 4; i++) {
                int m = warp_m * 64 + i * 16 + g;
                af[i][0] = As[buf][ks + t][m];
                af[i][1] = As[buf][ks + t][m + 8];
                af[i][2] = As[buf][ks + t + 4][m];
                af[i][3] = As[buf][ks + t + 4][m + 8];
            }
#pragma unroll
            for (int j = 0; j < 4; j++) {
                int n = warp_n * 32 + j * 8 + g;
                bf[j][0] = Bs[buf][ks + t][n];
                bf[j][1] = Bs[buf][ks + t + 4][n];
            }
#pragma unroll
            for (int i = 0; i < 4; i++)
#pragma unroll
                for (int j = 0; j < 4; j++)
                    mma8(c[i][j], af[i], bf[j]);
        }

        // store next stage
        if (has_next) {
            const int nb = buf ^ 1;
#pragma unroll
            for (int it = 0; it < 2; it++) {
                As[nb][lkq[it] + 0][lr[it]] = f2tf(pa[it].x);
                As[nb][lkq[it] + 1][lr[it]] = f2tf(pa[it].y);
                As[nb][lkq[it] + 2][lr[it]] = f2tf(pa[it].z);
                As[nb][lkq[it] + 3][lr[it]] = f2tf(pa[it].w);
                Bs[nb][lkq[it] + 0][lr[it]] = f2tf(pb[it].x);
                Bs[nb][lkq[it] + 1][lr[it]] = f2tf(pb[it].y);
                Bs[nb][lkq[it] + 2][lr[it]] = f2tf(pb[it].z);
                Bs[nb][lkq[it] + 3][lr[it]] = f2tf(pb[it].w);
            }
        }
        __syncthreads();
    }

#pragma unroll
    for (int i = 0; i < 4; i++) {
        int rm = row0 + warp_m * 64 + i * 16 + g;
#pragma unroll
        for (int j = 0; j < 4; j++) {
            int cn = col0 + warp_n * 32 + j * 8 + 2 * t;
            float b0 = bias[cn], b1 = bias[cn + 1];
            float2 v0 = make_float2(c[i][j][0] + b0, c[i][j][1] + b1);
            float2 v1 = make_float2(c[i][j][2] + b0, c[i][j][3] + b1);
            *(float2*)&C[(size_t)rm * N + cn]       = v0;
            *(float2*)&C[(size_t)(rm + 8) * N + cn] = v1;
        }
    }
}

// ---------------------------------------------------------------------------
// Flash attention v2 on tf32 tensor cores.
// Block: 256 threads (8 warps), 128-query tile; warp owns 16 rows.
// K stored transposed [d][key] (stride 72), V [key][d] (stride 72), tf32.
// P round-trips through smem (region also holds K; K uses 64 of the 128
// P rows). DYNAMIC shared memory (55.5 KB > 48 KB static limit).
// ---------------------------------------------------------------------------
#define FLD 72
#define FLASH_SMEM_BYTES ((128 * FLD + 64 * FLD) * 4 + 64 * 4)

__global__ __launch_bounds__(256)
void flash_tc(const float* __restrict__ Q, const float* __restrict__ K,
              const float* __restrict__ V, float* __restrict__ O)
{
    extern __shared__ uint32_t smem[];
    uint32_t* sKP = smem;                 // Ks[d][key] (64 rows), Ps[row][key] (128 rows)
    uint32_t* sV  = smem + 128 * FLD;     // Vs[key][d]
    float*    sPad = (float*)(smem + 128 * FLD + 64 * FLD);

    const int qt  = gridDim.x - 1 - blockIdx.x;   // biggest blocks first
    const int h   = blockIdx.y;
    const int bb  = blockIdx.z;
    const int tid = threadIdx.x;
    const int lane = tid & 31;
    const int w    = tid >> 5;   // warp 0..7
    const int g    = lane >> 2;  // 0..7
    const int t    = lane & 3;   // 0..3
    const int hoff = h * HD;

    const int qlow  = qt * 128 + w * 16 + g;
    const int qhigh = qlow + 8;
    const size_t qrowbase = (size_t)(bb * S_LEN + qt * 128 + w * 16);

    // Q fragments (scaled by 1/8 = exact in tf32), register resident.
    uint32_t aQ[8][4];
#pragma unroll
    for (int kd = 0; kd < 8; kd++) {
        int cq = hoff + kd * 8 + t;
        aQ[kd][0] = f2tf(Q[(qrowbase + g) * DM + cq] * 0.125f);
        aQ[kd][1] = f2tf(Q[(qrowbase + g + 8) * DM + cq] * 0.125f);
        aQ[kd][2] = f2tf(Q[(qrowbase + g) * DM + cq + 4] * 0.125f);
        aQ[kd][3] = f2tf(Q[(qrowbase + g + 8) * DM + cq + 4] * 0.125f);
    }

    float m0 = -3.0e38f, m1 = -3.0e38f, l0 = 0.0f, l1 = 0.0f;
    float cO[8][4];
#pragma unroll
    for (int j = 0; j < 8; j++)
#pragma unroll
        for (int q = 0; q < 4; q++) cO[j][q] = 0.0f;

    const int ntiles = 2 * qt + 2;
    for (int kt = 0; kt < ntiles; kt++) {
        const int kbase = bb * S_LEN + kt * 64;
        __syncthreads();   // prior tile fully consumed
        // K tile: Ks[d][key] (transposed, tf32). 64 keys x 64 d.
#pragma unroll
        for (int it = 0; it < 4; it++) {
            int linear = it * 256 + tid;
            int key = linear & 63;
            int dq  = linear >> 6;   // 0..15
            float4 kv = *(const float4*)&K[(size_t)(kbase + key) * DM + hoff + dq * 4];
            sKP[(dq * 4 + 0) * FLD + key] = f2tf(kv.x);
            sKP[(dq * 4 + 1) * FLD + key] = f2tf(kv.y);
            sKP[(dq * 4 + 2) * FLD + key] = f2tf(kv.z);
            sKP[(dq * 4 + 3) * FLD + key] = f2tf(kv.w);
        }
        // V tile: Vs[key][d] (tf32)
#pragma unroll
        for (int it = 0; it < 4; it++) {
            int linear = it * 256 + tid;
            int key = linear >> 4;    // 0..63
            int dq  = linear & 15;
            float4 vv = *(const float4*)&V[(size_t)(kbase + key) * DM + hoff + dq * 4];
            sV[key * FLD + dq * 4 + 0] = f2tf(vv.x);
            sV[key * FLD + dq * 4 + 1] = f2tf(vv.y);
            sV[key * FLD + dq * 4 + 2] = f2tf(vv.z);
            sV[key * FLD + dq * 4 + 3] = f2tf(vv.w);
        }
        if (tid < 64) sPad[tid] = g_pad[kbase + tid];
        __syncthreads();

        // S = (Q/8) K^T : 16x64 per warp in 8 n-fragments
        float cS[8][4];
#pragma unroll
        for (int jn = 0; jn < 8; jn++) {
            cS[jn][0] = cS[jn][1] = cS[jn][2] = cS[jn][3] = 0.0f;
#pragma unroll
            for (int kd = 0; kd < 8; kd++) {
                uint32_t bK[2];
                bK[0] = sKP[(kd * 8 + t) * FLD + jn * 8 + g];
                bK[1] = sKP[(kd * 8 + t + 4) * FLD + jn * 8 + g];
                mma8(cS[jn], aQ[kd], bK);
            }
        }

        // mask (causal + pad); masked -> exactly -1e9
        float mx0 = -3.0e38f, mx1 = -3.0e38f;
#pragma unroll
        for (int jn = 0; jn < 8; jn++) {
            int col = jn * 8 + 2 * t;
            int k0g = kt * 64 + col;
            bool p0 = (sPad[col] == 0.0f);
            bool p1 = (sPad[col + 1] == 0.0f);
            cS[jn][0] = (k0g     <= qlow  && p0) ? cS[jn][0] : -1.0e9f;
            cS[jn][1] = (k0g + 1 <= qlow  && p1) ? cS[jn][1] : -1.0e9f;
            cS[jn][2] = (k0g     <= qhigh && p0) ? cS[jn][2] : -1.0e9f;
            cS[jn][3] = (k0g + 1 <= qhigh && p1) ? cS[jn][3] : -1.0e9f;
            mx0 = fmaxf(mx0, fmaxf(cS[jn][0], cS[jn][1]));
            mx1 = fmaxf(mx1, fmaxf(cS[jn][2], cS[jn][3]));
        }
        mx0 = fmaxf(mx0, __shfl_xor_sync(0xffffffffu, mx0, 1));
        mx0 = fmaxf(mx0, __shfl_xor_sync(0xffffffffu, mx0, 2));
        mx1 = fmaxf(mx1, __shfl_xor_sync(0xffffffffu, mx1, 1));
        mx1 = fmaxf(mx1, __shfl_xor_sync(0xffffffffu, mx1, 2));

        float mn0 = fmaxf(m0, mx0), mn1 = fmaxf(m1, mx1);
        float cor0 = __expf(m0 - mn0), cor1 = __expf(m1 - mn1);

        float rs0 = 0.0f, rs1 = 0.0f;
#pragma unroll
        for (int jn = 0; jn < 8; jn++) {
            cS[jn][0] = __expf(cS[jn][0] - mn0);
            cS[jn][1] = __expf(cS[jn][1] - mn0);
            cS[jn][2] = __expf(cS[jn][2] - mn1);
            cS[jn][3] = __expf(cS[jn][3] - mn1);
            rs0 += cS[jn][0] + cS[jn][1];
            rs1 += cS[jn][2] + cS[jn][3];
            cO[jn][0] *= cor0; cO[jn][1] *= cor0;
            cO[jn][2] *= cor1; cO[jn][3] *= cor1;
        }
        rs0 += __shfl_xor_sync(0xffffffffu, rs0, 1);
        rs0 += __shfl_xor_sync(0xffffffffu, rs0, 2);
        rs1 += __shfl_xor_sync(0xffffffffu, rs1, 1);
        rs1 += __shfl_xor_sync(0xffffffffu, rs1, 2);
        l0 = l0 * cor0 + rs0;
        l1 = l1 * cor1 + rs1;
        m0 = mn0; m1 = mn1;

        __syncthreads();   // all warps done reading Ks before Ps overwrites it

        // P -> smem (tf32 a-operand layout: Ps[row][key], stride FLD)
        {
            int pr0 = (w * 16 + g) * FLD;
            int pr1 = (w * 16 + g + 8) * FLD;
#pragma unroll
            for (int jn = 0; jn < 8; jn++) {
                int pc = jn * 8 + 2 * t;
                sKP[pr0 + pc]     = f2tf(cS[jn][0]);
                sKP[pr0 + pc + 1] = f2tf(cS[jn][1]);
                sKP[pr1 + pc]     = f2tf(cS[jn][2]);
                sKP[pr1 + pc + 1] = f2tf(cS[jn][3]);
            }
        }
        __syncwarp();

        // O += P V
        {
            int pr0 = (w * 16 + g) * FLD;
            int pr1 = (w * 16 + g + 8) * FLD;
#pragma unroll
            for (int kd = 0; kd < 8; kd++) {
                uint32_t aP[4];
                aP[0] = sKP[pr0 + kd * 8 + t];
                aP[1] = sKP[pr1 + kd * 8 + t];
                aP[2] = sKP[pr0 + kd * 8 + t + 4];
                aP[3] = sKP[pr1 + kd * 8 + t + 4];
#pragma unroll
                for (int jn = 0; jn < 8; jn++) {
                    uint32_t bV[2];
                    bV[0] = sV[(kd * 8 + t) * FLD + jn * 8 + g];
                    bV[1] = sV[(kd * 8 + t + 4) * FLD + jn * 8 + g];
                    mma8(cO[jn], aP, bV);
                }
            }
        }
    }

    // Degenerate rows (entire causal prefix padded): reference softmax is
    // uniform over ALL S_LEN keys. Essentially never taken; exact when taken.
    if (m0 <= -9.9e8f) {
        l0 = (float)S_LEN;
#pragma unroll
        for (int jn = 0; jn < 8; jn++) {
            int d0 = hoff + jn * 8 + 2 * t;
            float s0 = 0.0f, s1 = 0.0f;
            for (int key = 0; key < S_LEN; key++) {
                const float* vp = V + (size_t)(bb * S_LEN + key) * DM + d0;
                s0 += vp[0]; s1 += vp[1];
            }
            cO[jn][0] = s0; cO[jn][1] = s1;
        }
    }
    if (m1 <= -9.9e8f) {
        l1 = (float)S_LEN;
#pragma unroll
        for (int jn = 0; jn < 8; jn++) {
            int d0 = hoff + jn * 8 + 2 * t;
            float s0 = 0.0f, s1 = 0.0f;
            for (int key = 0; key < S_LEN; key++) {
                const float* vp = V + (size_t)(bb * S_LEN + key) * DM + d0;
                s0 += vp[0]; s1 += vp[1];
            }
            cO[jn][2] = s0; cO[jn][3] = s1;
        }
    }

    const float il0 = 1.0f / l0, il1 = 1.0f / l1;
    const size_t or0 = (qrowbase + g) * DM + hoff;
    const size_t or1 = (qrowbase + g + 8) * DM + hoff;
#pragma unroll
    for (int jn = 0; jn < 8; jn++) {
        int dc = jn * 8 + 2 * t;
        *(float2*)&O[or0 + dc] = make_float2(cO[jn][0] * il0, cO[jn][1] * il0);
        *(float2*)&O[or1 + dc] = make_float2(cO[jn][2] * il1, cO[jn][3] * il1);
    }
}

// ---------------------------------------------------------------------------
extern "C" void kernel_launch(void* const* d_in, const int* in_sizes, int n_in,
                              void* d_out, int out_size)
{
    const float* x   = (const float*)d_in[0];
    const int*   ids = (const int*)  d_in[1];
    const float* Wq  = (const float*)d_in[2];
    const float* bq  = (const float*)d_in[3];
    const float* Wk  = (const float*)d_in[4];
    const float* bk  = (const float*)d_in[5];
    const float* Wv  = (const float*)d_in[6];
    const float* bv  = (const float*)d_in[7];
    const float* Wo  = (const float*)d_in[8];
    const float* bo  = (const float*)d_in[9];
    float* out = (float*)d_out;

    float *Qp, *Kp, *Vp, *Op;
    cudaGetSymbolAddress((void**)&Qp, g_Q);
    cudaGetSymbolAddress((void**)&Kp, g_K);
    cudaGetSymbolAddress((void**)&Vp, g_V);
    cudaGetSymbolAddress((void**)&Op, g_O);

    // Raise dynamic smem limit for flash_tc (idempotent; not a stream op,
    // no allocation — safe under graph capture).
    cudaFuncSetAttribute(flash_tc, cudaFuncAttributeMaxDynamicSharedMemorySize,
                         FLASH_SMEM_BYTES);

    pad_kernel<<<1, 256>>>(ids);

    dim3 gg(DM / 128, M_TOT / 128);   // (8, 32)
    gemm_tf32<<<gg, 256>>>(x, Wq, bq, Qp, M_TOT, DM, DM);
    gemm_tf32<<<gg, 256>>>(x, Wk, bk, Kp, M_TOT, DM, DM);
    gemm_tf32<<<gg, 256>>>(x, Wv, bv, Vp, M_TOT, DM, DM);

    dim3 gf(S_LEN / 128, NH, BATCH);  // (16, 16, 2)
    flash_tc<<<gf, 256, FLASH_SMEM_BYTES>>>(Qp, Kp, Vp, Op);

    gemm_tf32<<<gg, 256>>>(Op, Wo, bo, out, M_TOT, DM, DM);
}

// round 6
// speedup vs baseline: 1.0659x; 1.0659x over previous
#include <cuda_runtime.h>
#include <cstdint>

#define S_LEN 2048
#define DM    1024
#define NH    16
#define HD    64
#define BATCH 2
#define M_TOT (BATCH * S_LEN)   // 4096

// ---------------- scratch (device globals: no allocation allowed) ----------
__device__ float g_Q[M_TOT * DM];
__device__ float g_K[M_TOT * DM];
__device__ float g_V[M_TOT * DM];
__device__ float g_O[M_TOT * DM];
__device__ float g_pad[BATCH * S_LEN];   // 1.0f = padded (id==0), 0.0f = valid

// ---------------------------------------------------------------------------
__device__ __forceinline__ uint32_t f2tf(float f) {
    uint32_t u;
    asm("cvt.rna.tf32.f32 %0, %1;" : "=r"(u) : "f"(f));
    return u;
}

__device__ __forceinline__ void mma8(float* c, const uint32_t* a, const uint32_t* b) {
    asm volatile(
        "mma.sync.aligned.m16n8k8.row.col.f32.tf32.tf32.f32 "
        "{%0,%1,%2,%3},{%4,%5,%6,%7},{%8,%9},{%0,%1,%2,%3};"
        : "+f"(c[0]), "+f"(c[1]), "+f"(c[2]), "+f"(c[3])
        : "r"(a[0]), "r"(a[1]), "r"(a[2]), "r"(a[3]), "r"(b[0]), "r"(b[1]));
}

// ---------------------------------------------------------------------------
// Pad-flag kernel with int32/int64 dtype sniffing (see R0 notes).
// ---------------------------------------------------------------------------
__global__ void pad_kernel(const int* __restrict__ ids)
{
    __shared__ int orv;
    if (threadIdx.x == 0) orv = 0;
    __syncthreads();
    int local = 0;
    for (int i = threadIdx.x; i < 2048; i += blockDim.x)
        local |= ids[2 * i + 1];
    atomicOr(&orv, local);
    __syncthreads();
    bool is64 = (orv == 0);
    for (int i = threadIdx.x; i < BATCH * S_LEN; i += blockDim.x) {
        int nz = is64 ? ((ids[2 * i] | ids[2 * i + 1]) != 0) : (ids[i] != 0);
        g_pad[i] = nz ? 0.0f : 1.0f;
    }
}

// ---------------------------------------------------------------------------
// TF32 tensor-core GEMM (NT), double-buffered, FRAGMENT-PACKED smem.
// C[m][n] = sum_k A[m][k]*W[n][k] + bias[n]
// 128x128 tile, BK=16 (2 sh-halves of 8), 8 warps (64x32 warp tiles).
// Asm uint4 slot = full a-fragment; Bsm uint2 slot = full b-fragment.
// Slice stride 264 words -> conflict-free vector reads.
// ---------------------------------------------------------------------------
#define ASL 264
#define BSL 264

__global__ __launch_bounds__(256, 2)
void gemm_tf32(const float* __restrict__ A, const float* __restrict__ W,
               const float* __restrict__ bias, float* __restrict__ C,
               int M, int N, int K)
{
    __shared__ uint32_t Asm[2][2][4][ASL];   // [stage][sh][t][mt*32+g*4+comp]
    __shared__ uint32_t Bsm[2][2][4][BSL];   // [stage][sh][t][n*2+comp]

    const int tid  = threadIdx.x;
    const int lane = tid & 31;
    const int wid  = tid >> 5;
    const int g    = lane >> 2;   // 0..7
    const int t    = lane & 3;    // 0..3
    const int warp_m = wid & 1;   // 0..1 (64 rows each)
    const int warp_n = wid >> 1;  // 0..3 (32 cols each)

    const int row0 = blockIdx.y * 128;
    const int col0 = blockIdx.x * 128;

    // loader mapping: thread handles (row lr, k-quad lkq) twice
    int lr[2], lkq[2];
#pragma unroll
    for (int it = 0; it < 2; it++) {
        int linear = it * 256 + tid;
        lr[it]  = (linear & 31) | ((linear >> 7) << 5);
        lkq[it] = ((linear >> 5) & 3) * 4;
    }
    // writer constants per slot
    int w_sh[2], w_aoff[2], w_boff[2];
#pragma unroll
    for (int it = 0; it < 2; it++) {
        int kq = lkq[it], row = lr[it];
        int sh = kq >> 3;
        int rh = (kq >> 2) & 1;          // 0: t-reg pair, 1: t+4-reg pair
        int mt = row >> 4, gg = row & 7, rhi = (row >> 3) & 1;
        w_sh[it]   = sh;
        w_aoff[it] = mt * 32 + gg * 4 + (rh * 2 + rhi);
        w_boff[it] = row * 2 + rh;       // component within uint2 (B)
    }

    const float* Ap[2] = { A + (size_t)(row0 + lr[0]) * K + lkq[0],
                           A + (size_t)(row0 + lr[1]) * K + lkq[1] };
    const float* Wp[2] = { W + (size_t)(col0 + lr[0]) * K + lkq[0],
                           W + (size_t)(col0 + lr[1]) * K + lkq[1] };

    float c[4][4][4];
#pragma unroll
    for (int i = 0; i < 4; i++)
#pragma unroll
        for (int j = 0; j < 4; j++)
#pragma unroll
            for (int q = 0; q < 4; q++) c[i][j][q] = 0.0f;

    // prologue: fill stage 0
    {
#pragma unroll
        for (int it = 0; it < 2; it++) {
            float4 pa = *(const float4*)(Ap[it]);
            float4 pb = *(const float4*)(Wp[it]);
            Asm[0][w_sh[it]][0][w_aoff[it]] = f2tf(pa.x);
            Asm[0][w_sh[it]][1][w_aoff[it]] = f2tf(pa.y);
            Asm[0][w_sh[it]][2][w_aoff[it]] = f2tf(pa.z);
            Asm[0][w_sh[it]][3][w_aoff[it]] = f2tf(pa.w);
            Bsm[0][w_sh[it]][0][w_boff[it]] = f2tf(pb.x);
            Bsm[0][w_sh[it]][1][w_boff[it]] = f2tf(pb.y);
            Bsm[0][w_sh[it]][2][w_boff[it]] = f2tf(pb.z);
            Bsm[0][w_sh[it]][3][w_boff[it]] = f2tf(pb.w);
        }
    }
    __syncthreads();

    const int a_rd = warp_m * 128;
    const int b_rd = (warp_n * 32) * 2;

    for (int k0 = 0; k0 < K; k0 += 16) {
        const int buf = (k0 >> 4) & 1;
        const bool has_next = (k0 + 16) < K;

        float4 pa[2], pb[2];
        if (has_next) {
#pragma unroll
            for (int it = 0; it < 2; it++) {
                pa[it] = *(const float4*)(Ap[it] + k0 + 16);
                pb[it] = *(const float4*)(Wp[it] + k0 + 16);
            }
        }

        // compute on current stage: 2 sh-halves x 16 MMAs
#pragma unroll
        for (int sh = 0; sh < 2; sh++) {
            uint4 af[4];
            uint2 bf[4];
#pragma unroll
            for (int i = 0; i < 4; i++)
                af[i] = *(const uint4*)&Asm[buf][sh][t][a_rd + i * 32 + g * 4];
#pragma unroll
            for (int j = 0; j < 4; j++)
                bf[j] = *(const uint2*)&Bsm[buf][sh][t][b_rd + (j * 8 + g) * 2];
#pragma unroll
            for (int i = 0; i < 4; i++)
#pragma unroll
                for (int j = 0; j < 4; j++)
                    mma8(c[i][j], (const uint32_t*)&af[i], (const uint32_t*)&bf[j]);
        }

        // store next stage
        if (has_next) {
            const int nb = buf ^ 1;
#pragma unroll
            for (int it = 0; it < 2; it++) {
                Asm[nb][w_sh[it]][0][w_aoff[it]] = f2tf(pa[it].x);
                Asm[nb][w_sh[it]][1][w_aoff[it]] = f2tf(pa[it].y);
                Asm[nb][w_sh[it]][2][w_aoff[it]] = f2tf(pa[it].z);
                Asm[nb][w_sh[it]][3][w_aoff[it]] = f2tf(pa[it].w);
                Bsm[nb][w_sh[it]][0][w_boff[it]] = f2tf(pb[it].x);
                Bsm[nb][w_sh[it]][1][w_boff[it]] = f2tf(pb[it].y);
                Bsm[nb][w_sh[it]][2][w_boff[it]] = f2tf(pb[it].z);
                Bsm[nb][w_sh[it]][3][w_boff[it]] = f2tf(pb[it].w);
            }
        }
        __syncthreads();
    }

#pragma unroll
    for (int i = 0; i < 4; i++) {
        int rm = row0 + warp_m * 64 + i * 16 + g;
#pragma unroll
        for (int j = 0; j < 4; j++) {
            int cn = col0 + warp_n * 32 + j * 8 + 2 * t;
            float b0 = bias[cn], b1 = bias[cn + 1];
            float2 v0 = make_float2(c[i][j][0] + b0, c[i][j][1] + b1);
            float2 v1 = make_float2(c[i][j][2] + b0, c[i][j][3] + b1);
            *(float2*)&C[(size_t)rm * N + cn]       = v0;
            *(float2*)&C[(size_t)(rm + 8) * N + cn] = v1;
        }
    }
}

// ---------------------------------------------------------------------------
// Flash attention v2 on tf32 tensor cores. (unchanged from R4 — passing)
// Block: 256 threads (8 warps), 128-query tile; warp owns 16 rows.
// ---------------------------------------------------------------------------
#define FLD 72
#define FLASH_SMEM_BYTES ((128 * FLD + 64 * FLD) * 4 + 64 * 4)

__global__ __launch_bounds__(256)
void flash_tc(const float* __restrict__ Q, const float* __restrict__ K,
              const float* __restrict__ V, float* __restrict__ O)
{
    extern __shared__ uint32_t smem[];
    uint32_t* sKP = smem;                 // Ks[d][key] (64 rows), Ps[row][key] (128 rows)
    uint32_t* sV  = smem + 128 * FLD;     // Vs[key][d]
    float*    sPad = (float*)(smem + 128 * FLD + 64 * FLD);

    const int qt  = gridDim.x - 1 - blockIdx.x;   // biggest blocks first
    const int h   = blockIdx.y;
    const int bb  = blockIdx.z;
    const int tid = threadIdx.x;
    const int lane = tid & 31;
    const int w    = tid >> 5;   // warp 0..7
    const int g    = lane >> 2;  // 0..7
    const int t    = lane & 3;   // 0..3
    const int hoff = h * HD;

    const int qlow  = qt * 128 + w * 16 + g;
    const int qhigh = qlow + 8;
    const size_t qrowbase = (size_t)(bb * S_LEN + qt * 128 + w * 16);

    uint32_t aQ[8][4];
#pragma unroll
    for (int kd = 0; kd < 8; kd++) {
        int cq = hoff + kd * 8 + t;
        aQ[kd][0] = f2tf(Q[(qrowbase + g) * DM + cq] * 0.125f);
        aQ[kd][1] = f2tf(Q[(qrowbase + g + 8) * DM + cq] * 0.125f);
        aQ[kd][2] = f2tf(Q[(qrowbase + g) * DM + cq + 4] * 0.125f);
        aQ[kd][3] = f2tf(Q[(qrowbase + g + 8) * DM + cq + 4] * 0.125f);
    }

    float m0 = -3.0e38f, m1 = -3.0e38f, l0 = 0.0f, l1 = 0.0f;
    float cO[8][4];
#pragma unroll
    for (int j = 0; j < 8; j++)
#pragma unroll
        for (int q = 0; q < 4; q++) cO[j][q] = 0.0f;

    const int ntiles = 2 * qt + 2;
    for (int kt = 0; kt < ntiles; kt++) {
        const int kbase = bb * S_LEN + kt * 64;
        __syncthreads();
#pragma unroll
        for (int it = 0; it < 4; it++) {
            int linear = it * 256 + tid;
            int key = linear & 63;
            int dq  = linear >> 6;
            float4 kv = *(const float4*)&K[(size_t)(kbase + key) * DM + hoff + dq * 4];
            sKP[(dq * 4 + 0) * FLD + key] = f2tf(kv.x);
            sKP[(dq * 4 + 1) * FLD + key] = f2tf(kv.y);
            sKP[(dq * 4 + 2) * FLD + key] = f2tf(kv.z);
            sKP[(dq * 4 + 3) * FLD + key] = f2tf(kv.w);
        }
#pragma unroll
        for (int it = 0; it < 4; it++) {
            int linear = it * 256 + tid;
            int key = linear >> 4;
            int dq  = linear & 15;
            float4 vv = *(const float4*)&V[(size_t)(kbase + key) * DM + hoff + dq * 4];
            sV[key * FLD + dq * 4 + 0] = f2tf(vv.x);
            sV[key * FLD + dq * 4 + 1] = f2tf(vv.y);
            sV[key * FLD + dq * 4 + 2] = f2tf(vv.z);
            sV[key * FLD + dq * 4 + 3] = f2tf(vv.w);
        }
        if (tid < 64) sPad[tid] = g_pad[kbase + tid];
        __syncthreads();

        float cS[8][4];
#pragma unroll
        for (int jn = 0; jn < 8; jn++) {
            cS[jn][0] = cS[jn][1] = cS[jn][2] = cS[jn][3] = 0.0f;
#pragma unroll
            for (int kd = 0; kd < 8; kd++) {
                uint32_t bK[2];
                bK[0] = sKP[(kd * 8 + t) * FLD + jn * 8 + g];
                bK[1] = sKP[(kd * 8 + t + 4) * FLD + jn * 8 + g];
                mma8(cS[jn], aQ[kd], bK);
            }
        }

        float mx0 = -3.0e38f, mx1 = -3.0e38f;
#pragma unroll
        for (int jn = 0; jn < 8; jn++) {
            int col = jn * 8 + 2 * t;
            int k0g = kt * 64 + col;
            bool p0 = (sPad[col] == 0.0f);
            bool p1 = (sPad[col + 1] == 0.0f);
            cS[jn][0] = (k0g     <= qlow  && p0) ? cS[jn][0] : -1.0e9f;
            cS[jn][1] = (k0g + 1 <= qlow  && p1) ? cS[jn][1] : -1.0e9f;
            cS[jn][2] = (k0g     <= qhigh && p0) ? cS[jn][2] : -1.0e9f;
            cS[jn][3] = (k0g + 1 <= qhigh && p1) ? cS[jn][3] : -1.0e9f;
            mx0 = fmaxf(mx0, fmaxf(cS[jn][0], cS[jn][1]));
            mx1 = fmaxf(mx1, fmaxf(cS[jn][2], cS[jn][3]));
        }
        mx0 = fmaxf(mx0, __shfl_xor_sync(0xffffffffu, mx0, 1));
        mx0 = fmaxf(mx0, __shfl_xor_sync(0xffffffffu, mx0, 2));
        mx1 = fmaxf(mx1, __shfl_xor_sync(0xffffffffu, mx1, 1));
        mx1 = fmaxf(mx1, __shfl_xor_sync(0xffffffffu, mx1, 2));

        float mn0 = fmaxf(m0, mx0), mn1 = fmaxf(m1, mx1);
        float cor0 = __expf(m0 - mn0), cor1 = __expf(m1 - mn1);

        float rs0 = 0.0f, rs1 = 0.0f;
#pragma unroll
        for (int jn = 0; jn < 8; jn++) {
            cS[jn][0] = __expf(cS[jn][0] - mn0);
            cS[jn][1] = __expf(cS[jn][1] - mn0);
            cS[jn][2] = __expf(cS[jn][2] - mn1);
            cS[jn][3] = __expf(cS[jn][3] - mn1);
            rs0 += cS[jn][0] + cS[jn][1];
            rs1 += cS[jn][2] + cS[jn][3];
            cO[jn][0] *= cor0; cO[jn][1] *= cor0;
            cO[jn][2] *= cor1; cO[jn][3] *= cor1;
        }
        rs0 += __shfl_xor_sync(0xffffffffu, rs0, 1);
        rs0 += __shfl_xor_sync(0xffffffffu, rs0, 2);
        rs1 += __shfl_xor_sync(0xffffffffu, rs1, 1);
        rs1 += __shfl_xor_sync(0xffffffffu, rs1, 2);
        l0 = l0 * cor0 + rs0;
        l1 = l1 * cor1 + rs1;
        m0 = mn0; m1 = mn1;

        __syncthreads();

        {
            int pr0 = (w * 16 + g) * FLD;
            int pr1 = (w * 16 + g + 8) * FLD;
#pragma unroll
            for (int jn = 0; jn < 8; jn++) {
                int pc = jn * 8 + 2 * t;
                sKP[pr0 + pc]     = f2tf(cS[jn][0]);
                sKP[pr0 + pc + 1] = f2tf(cS[jn][1]);
                sKP[pr1 + pc]     = f2tf(cS[jn][2]);
                sKP[pr1 + pc + 1] = f2tf(cS[jn][3]);
            }
        }
        __syncwarp();

        {
            int pr0 = (w * 16 + g) * FLD;
            int pr1 = (w * 16 + g + 8) * FLD;
#pragma unroll
            for (int kd = 0; kd < 8; kd++) {
                uint32_t aP[4];
                aP[0] = sKP[pr0 + kd * 8 + t];
                aP[1] = sKP[pr1 + kd * 8 + t];
                aP[2] = sKP[pr0 + kd * 8 + t + 4];
                aP[3] = sKP[pr1 + kd * 8 + t + 4];
#pragma unroll
                for (int jn = 0; jn < 8; jn++) {
                    uint32_t bV[2];
                    bV[0] = sV[(kd * 8 + t) * FLD + jn * 8 + g];
                    bV[1] = sV[(kd * 8 + t + 4) * FLD + jn * 8 + g];
                    mma8(cO[jn], aP, bV);
                }
            }
        }
    }

    if (m0 <= -9.9e8f) {
        l0 = (float)S_LEN;
#pragma unroll
        for (int jn = 0; jn < 8; jn++) {
            int d0 = hoff + jn * 8 + 2 * t;
            float s0 = 0.0f, s1 = 0.0f;
            for (int key = 0; key < S_LEN; key++) {
                const float* vp = V + (size_t)(bb * S_LEN + key) * DM + d0;
                s0 += vp[0]; s1 += vp[1];
            }
            cO[jn][0] = s0; cO[jn][1] = s1;
        }
    }
    if (m1 <= -9.9e8f) {
        l1 = (float)S_LEN;
#pragma unroll
        for (int jn = 0; jn < 8; jn++) {
            int d0 = hoff + jn * 8 + 2 * t;
            float s0 = 0.0f, s1 = 0.0f;
            for (int key = 0; key < S_LEN; key++) {
                const float* vp = V + (size_t)(bb * S_LEN + key) * DM + d0;
                s0 += vp[0]; s1 += vp[1];
            }
            cO[jn][2] = s0; cO[jn][3] = s1;
        }
    }

    const float il0 = 1.0f / l0, il1 = 1.0f / l1;
    const size_t or0 = (qrowbase + g) * DM + hoff;
    const size_t or1 = (qrowbase + g + 8) * DM + hoff;
#pragma unroll
    for (int jn = 0; jn < 8; jn++) {
        int dc = jn * 8 + 2 * t;
        *(float2*)&O[or0 + dc] = make_float2(cO[jn][0] * il0, cO[jn][1] * il0);
        *(float2*)&O[or1 + dc] = make_float2(cO[jn][2] * il1, cO[jn][3] * il1);
    }
}

// ---------------------------------------------------------------------------
extern "C" void kernel_launch(void* const* d_in, const int* in_sizes, int n_in,
                              void* d_out, int out_size)
{
    const float* x   = (const float*)d_in[0];
    const int*   ids = (const int*)  d_in[1];
    const float* Wq  = (const float*)d_in[2];
    const float* bq  = (const float*)d_in[3];
    const float* Wk  = (const float*)d_in[4];
    const float* bk  = (const float*)d_in[5];
    const float* Wv  = (const float*)d_in[6];
    const float* bv  = (const float*)d_in[7];
    const float* Wo  = (const float*)d_in[8];
    const float* bo  = (const float*)d_in[9];
    float* out = (float*)d_out;

    float *Qp, *Kp, *Vp, *Op;
    cudaGetSymbolAddress((void**)&Qp, g_Q);
    cudaGetSymbolAddress((void**)&Kp, g_K);
    cudaGetSymbolAddress((void**)&Vp, g_V);
    cudaGetSymbolAddress((void**)&Op, g_O);

    cudaFuncSetAttribute(flash_tc, cudaFuncAttributeMaxDynamicSharedMemorySize,
                         FLASH_SMEM_BYTES);

    pad_kernel<<<1, 256>>>(ids);

    dim3 gg(DM / 128, M_TOT / 128);   // (8, 32)
    gemm_tf32<<<gg, 256>>>(x, Wq, bq, Qp, M_TOT, DM, DM);
    gemm_tf32<<<gg, 256>>>(x, Wk, bk, Kp, M_TOT, DM, DM);
    gemm_tf32<<<gg, 256>>>(x, Wv, bv, Vp, M_TOT, DM, DM);

    dim3 gf(S_LEN / 128, NH, BATCH);  // (16, 16, 2)
    flash_tc<<<gf, 256, FLASH_SMEM_BYTES>>>(Qp, Kp, Vp, Op);

    gemm_tf32<<<gg, 256>>>(Op, Wo, bo, out, M_TOT, DM, DM);
}

// round 7
// speedup vs baseline: 1.4297x; 1.3413x over previous
#include <cuda_runtime.h>
#include <cstdint>

#define S_LEN 2048
#define DM    1024
#define NH    16
#define HD    64
#define BATCH 2
#define M_TOT (BATCH * S_LEN)   // 4096

// ---------------- scratch (device globals: no allocation allowed) ----------
__device__ float g_Q[M_TOT * DM];
__device__ float g_K[M_TOT * DM];
__device__ float g_V[M_TOT * DM];
__device__ float g_O[M_TOT * DM];
__device__ float g_X[M_TOT * DM];          // tf32-rounded x
__device__ float g_WR[4][DM * DM];         // tf32-rounded Wq,Wk,Wv,Wo
__device__ float g_pad[BATCH * S_LEN];     // 1.0f = padded (id==0), 0.0f = valid

// ---------------------------------------------------------------------------
__device__ __forceinline__ uint32_t f2tf(float f) {
    uint32_t u;
    asm("cvt.rna.tf32.f32 %0, %1;" : "=r"(u) : "f"(f));
    return u;
}

__device__ __forceinline__ void mma8(float* c, const uint32_t* a, const uint32_t* b) {
    asm volatile(
        "mma.sync.aligned.m16n8k8.row.col.f32.tf32.tf32.f32 "
        "{%0,%1,%2,%3},{%4,%5,%6,%7},{%8,%9},{%0,%1,%2,%3};"
        : "+f"(c[0]), "+f"(c[1]), "+f"(c[2]), "+f"(c[3])
        : "r"(a[0]), "r"(a[1]), "r"(a[2]), "r"(a[3]), "r"(b[0]), "r"(b[1]));
}

__device__ __forceinline__ void cpa16(uint32_t dst, const float* src) {
    asm volatile("cp.async.cg.shared.global [%0], [%1], 16;" :: "r"(dst), "l"(src));
}

// ---------------------------------------------------------------------------
// Round fp32 -> tf32-representable fp32 (rna), float4 at a time.
// ---------------------------------------------------------------------------
__global__ void round_tf32(const float4* __restrict__ src, float4* __restrict__ dst, int n4)
{
    int i = blockIdx.x * blockDim.x + threadIdx.x;
    if (i < n4) {
        float4 v = src[i];
        float4 o;
        o.x = __uint_as_float(f2tf(v.x));
        o.y = __uint_as_float(f2tf(v.y));
        o.z = __uint_as_float(f2tf(v.z));
        o.w = __uint_as_float(f2tf(v.w));
        dst[i] = o;
    }
}

// ---------------------------------------------------------------------------
// Pad-flag kernel with int32/int64 dtype sniffing (see R0 notes).
// ---------------------------------------------------------------------------
__global__ void pad_kernel(const int* __restrict__ ids)
{
    __shared__ int orv;
    if (threadIdx.x == 0) orv = 0;
    __syncthreads();
    int local = 0;
    for (int i = threadIdx.x; i < 2048; i += blockDim.x)
        local |= ids[2 * i + 1];
    atomicOr(&orv, local);
    __syncthreads();
    bool is64 = (orv == 0);
    for (int i = threadIdx.x; i < BATCH * S_LEN; i += blockDim.x) {
        int nz = is64 ? ((ids[2 * i] | ids[2 * i + 1]) != 0) : (ids[i] != 0);
        g_pad[i] = nz ? 0.0f : 1.0f;
    }
}

// ---------------------------------------------------------------------------
// TF32 tensor-core GEMM (NT), cp.async 3-stage pipeline, BK=32.
// Inputs A, W MUST be tf32-rounded fp32 (pre-pass) — MMA reads raw bits.
// C[m][n] = sum_k A[m][k]*W[n][k] + bias[n]
// 128x128 tile, 8 warps (64x32 warp tiles), 64 MMAs/warp per barrier.
// Smem rows XOR-swizzled (chunk c ^ (row&7)) — conflict-free stores+reads.
// ---------------------------------------------------------------------------
#define GSTAGES 3
#define GSTAGE_WORDS (2 * 128 * 32)                       // A + B, 8192 words
#define GEMM_SMEM_BYTES (GSTAGES * GSTAGE_WORDS * 4)      // 96 KB

__global__ __launch_bounds__(256, 2)
void gemm_tf32(const float* __restrict__ A, const float* __restrict__ W,
               const float* __restrict__ bias, float* __restrict__ C,
               int M, int N, int K)
{
    extern __shared__ uint32_t sm[];

    const int tid  = threadIdx.x;
    const int lane = tid & 31;
    const int wid  = tid >> 5;
    const int g    = lane >> 2;   // 0..7
    const int t    = lane & 3;    // 0..3
    const int warp_m = wid & 1;   // 0..1 (64 rows each)
    const int warp_n = wid >> 1;  // 0..3 (32 cols each)

    const int row0 = blockIdx.y * 128;
    const int col0 = blockIdx.x * 128;

    // cp.async mapping: thread -> row (tid>>1), 4 chunks (16B) starting (tid&1)*4
    const int ldr  = tid >> 1;           // 0..127
    const int ldcb = (tid & 1) * 4;      // 0 or 4
    const float* Arow = A + (size_t)(row0 + ldr) * K;
    const float* Wrow = W + (size_t)(col0 + ldr) * K;
    uint32_t smbase;
    {
        void* p = (void*)sm;
        smbase = (uint32_t)__cvta_generic_to_shared(p);
    }
    // precomputed swizzled byte offsets for this thread's 4 chunks
    uint32_t adst[4], bdst[4];
#pragma unroll
    for (int cc = 0; cc < 4; cc++) {
        int c = ldcb + cc;
        uint32_t woff = (uint32_t)(ldr * 32 + ((c ^ (ldr & 7)) * 4));
        adst[cc] = smbase + woff * 4;
        bdst[cc] = smbase + (4096 + woff) * 4;
    }

    float c[4][4][4];
#pragma unroll
    for (int i = 0; i < 4; i++)
#pragma unroll
        for (int j = 0; j < 4; j++)
#pragma unroll
            for (int q = 0; q < 4; q++) c[i][j][q] = 0.0f;

    const int nIter = K / 32;    // 32

    // prefill stages 0,1
#pragma unroll
    for (int s = 0; s < GSTAGES - 1; s++) {
        uint32_t soff = (uint32_t)(s * GSTAGE_WORDS * 4);
        int k0 = s * 32;
#pragma unroll
        for (int cc = 0; cc < 4; cc++) {
            int c4 = (ldcb + cc) * 4;
            cpa16(adst[cc] + soff, Arow + k0 + c4);
            cpa16(bdst[cc] + soff, Wrow + k0 + c4);
        }
        asm volatile("cp.async.commit_group;");
    }

    const int a_m0 = warp_m * 64 + g;
    const int b_n0 = warp_n * 32 + g;

    for (int it = 0; it < nIter; it++) {
        asm volatile("cp.async.wait_group 1;");
        __syncthreads();

        const uint32_t* As = sm + (it % GSTAGES) * GSTAGE_WORDS;
        const uint32_t* Bs = As + 4096;

#pragma unroll
        for (int sh = 0; sh < 4; sh++) {
            const int ch0 = ((2 * sh) ^ g) * 4 + t;       // word off in row: k=8sh+t
            const int ch1 = ((2 * sh + 1) ^ g) * 4 + t;   // k=8sh+t+4
            uint32_t af[4][4];
            uint32_t bf[4][2];
#pragma unroll
            for (int i = 0; i < 4; i++) {
                int m = (a_m0 + i * 16) * 32;
                af[i][0] = As[m + ch0];
                af[i][1] = As[m + 256 + ch0];   // +8 rows
                af[i][2] = As[m + ch1];
                af[i][3] = As[m + 256 + ch1];
            }
#pragma unroll
            for (int j = 0; j < 4; j++) {
                int n = (b_n0 + j * 8) * 32;
                bf[j][0] = Bs[n + ch0];
                bf[j][1] = Bs[n + ch1];
            }
#pragma unroll
            for (int i = 0; i < 4; i++)
#pragma unroll
                for (int j = 0; j < 4; j++)
                    mma8(c[i][j], af[i], bf[j]);
        }

        // issue stage it+2 (into buffer (it-1)%3: safe — all warps passed barrier)
        int nk = (it + GSTAGES - 1) * 32;
        if (nk < K) {
            uint32_t soff = (uint32_t)(((it + GSTAGES - 1) % GSTAGES) * GSTAGE_WORDS * 4);
#pragma unroll
            for (int cc = 0; cc < 4; cc++) {
                int c4 = (ldcb + cc) * 4;
                cpa16(adst[cc] + soff, Arow + nk + c4);
                cpa16(bdst[cc] + soff, Wrow + nk + c4);
            }
        }
        asm volatile("cp.async.commit_group;");
    }

#pragma unroll
    for (int i = 0; i < 4; i++) {
        int rm = row0 + warp_m * 64 + i * 16 + g;
#pragma unroll
        for (int j = 0; j < 4; j++) {
            int cn = col0 + warp_n * 32 + j * 8 + 2 * t;
            float b0 = bias[cn], b1 = bias[cn + 1];
            float2 v0 = make_float2(c[i][j][0] + b0, c[i][j][1] + b1);
            float2 v1 = make_float2(c[i][j][2] + b0, c[i][j][3] + b1);
            *(float2*)&C[(size_t)rm * N + cn]       = v0;
            *(float2*)&C[(size_t)(rm + 8) * N + cn] = v1;
        }
    }
}

// ---------------------------------------------------------------------------
// Flash attention v2 on tf32 tensor cores. (R6 version; O stored tf32-rounded)
// Block: 256 threads (8 warps), 128-query tile; warp owns 16 rows.
// ---------------------------------------------------------------------------
#define FLD 72
#define FLASH_SMEM_BYTES ((128 * FLD + 64 * FLD) * 4 + 64 * 4)

__global__ __launch_bounds__(256)
void flash_tc(const float* __restrict__ Q, const float* __restrict__ K,
              const float* __restrict__ V, float* __restrict__ O)
{
    extern __shared__ uint32_t smem[];
    uint32_t* sKP = smem;                 // Ks[d][key] (64 rows), Ps[row][key] (128 rows)
    uint32_t* sV  = smem + 128 * FLD;     // Vs[key][d]
    float*    sPad = (float*)(smem + 128 * FLD + 64 * FLD);

    const int qt  = gridDim.x - 1 - blockIdx.x;   // biggest blocks first
    const int h   = blockIdx.y;
    const int bb  = blockIdx.z;
    const int tid = threadIdx.x;
    const int lane = tid & 31;
    const int w    = tid >> 5;   // warp 0..7
    const int g    = lane >> 2;  // 0..7
    const int t    = lane & 3;   // 0..3
    const int hoff = h * HD;

    const int qlow  = qt * 128 + w * 16 + g;
    const int qhigh = qlow + 8;
    const size_t qrowbase = (size_t)(bb * S_LEN + qt * 128 + w * 16);

    uint32_t aQ[8][4];
#pragma unroll
    for (int kd = 0; kd < 8; kd++) {
        int cq = hoff + kd * 8 + t;
        aQ[kd][0] = f2tf(Q[(qrowbase + g) * DM + cq] * 0.125f);
        aQ[kd][1] = f2tf(Q[(qrowbase + g + 8) * DM + cq] * 0.125f);
        aQ[kd][2] = f2tf(Q[(qrowbase + g) * DM + cq + 4] * 0.125f);
        aQ[kd][3] = f2tf(Q[(qrowbase + g + 8) * DM + cq + 4] * 0.125f);
    }

    float m0 = -3.0e38f, m1 = -3.0e38f, l0 = 0.0f, l1 = 0.0f;
    float cO[8][4];
#pragma unroll
    for (int j = 0; j < 8; j++)
#pragma unroll
        for (int q = 0; q < 4; q++) cO[j][q] = 0.0f;

    const int ntiles = 2 * qt + 2;
    for (int kt = 0; kt < ntiles; kt++) {
        const int kbase = bb * S_LEN + kt * 64;
        __syncthreads();
#pragma unroll
        for (int it = 0; it < 4; it++) {
            int linear = it * 256 + tid;
            int key = linear & 63;
            int dq  = linear >> 6;
            float4 kv = *(const float4*)&K[(size_t)(kbase + key) * DM + hoff + dq * 4];
            sKP[(dq * 4 + 0) * FLD + key] = f2tf(kv.x);
            sKP[(dq * 4 + 1) * FLD + key] = f2tf(kv.y);
            sKP[(dq * 4 + 2) * FLD + key] = f2tf(kv.z);
            sKP[(dq * 4 + 3) * FLD + key] = f2tf(kv.w);
        }
#pragma unroll
        for (int it = 0; it < 4; it++) {
            int linear = it * 256 + tid;
            int key = linear >> 4;
            int dq  = linear & 15;
            float4 vv = *(const float4*)&V[(size_t)(kbase + key) * DM + hoff + dq * 4];
            sV[key * FLD + dq * 4 + 0] = f2tf(vv.x);
            sV[key * FLD + dq * 4 + 1] = f2tf(vv.y);
            sV[key * FLD + dq * 4 + 2] = f2tf(vv.z);
            sV[key * FLD + dq * 4 + 3] = f2tf(vv.w);
        }
        if (tid < 64) sPad[tid] = g_pad[kbase + tid];
        __syncthreads();

        float cS[8][4];
#pragma unroll
        for (int jn = 0; jn < 8; jn++) {
            cS[jn][0] = cS[jn][1] = cS[jn][2] = cS[jn][3] = 0.0f;
#pragma unroll
            for (int kd = 0; kd < 8; kd++) {
                uint32_t bK[2];
                bK[0] = sKP[(kd * 8 + t) * FLD + jn * 8 + g];
                bK[1] = sKP[(kd * 8 + t + 4) * FLD + jn * 8 + g];
                mma8(cS[jn], aQ[kd], bK);
            }
        }

        float mx0 = -3.0e38f, mx1 = -3.0e38f;
#pragma unroll
        for (int jn = 0; jn < 8; jn++) {
            int col = jn * 8 + 2 * t;
            int k0g = kt * 64 + col;
            bool p0 = (sPad[col] == 0.0f);
            bool p1 = (sPad[col + 1] == 0.0f);
            cS[jn][0] = (k0g     <= qlow  && p0) ? cS[jn][0] : -1.0e9f;
            cS[jn][1] = (k0g + 1 <= qlow  && p1) ? cS[jn][1] : -1.0e9f;
            cS[jn][2] = (k0g     <= qhigh && p0) ? cS[jn][2] : -1.0e9f;
            cS[jn][3] = (k0g + 1 <= qhigh && p1) ? cS[jn][3] : -1.0e9f;
            mx0 = fmaxf(mx0, fmaxf(cS[jn][0], cS[jn][1]));
            mx1 = fmaxf(mx1, fmaxf(cS[jn][2], cS[jn][3]));
        }
        mx0 = fmaxf(mx0, __shfl_xor_sync(0xffffffffu, mx0, 1));
        mx0 = fmaxf(mx0, __shfl_xor_sync(0xffffffffu, mx0, 2));
        mx1 = fmaxf(mx1, __shfl_xor_sync(0xffffffffu, mx1, 1));
        mx1 = fmaxf(mx1, __shfl_xor_sync(0xffffffffu, mx1, 2));

        float mn0 = fmaxf(m0, mx0), mn1 = fmaxf(m1, mx1);
        float cor0 = __expf(m0 - mn0), cor1 = __expf(m1 - mn1);

        float rs0 = 0.0f, rs1 = 0.0f;
#pragma unroll
        for (int jn = 0; jn < 8; jn++) {
            cS[jn][0] = __expf(cS[jn][0] - mn0);
            cS[jn][1] = __expf(cS[jn][1] - mn0);
            cS[jn][2] = __expf(cS[jn][2] - mn1);
            cS[jn][3] = __expf(cS[jn][3] - mn1);
            rs0 += cS[jn][0] + cS[jn][1];
            rs1 += cS[jn][2] + cS[jn][3];
            cO[jn][0] *= cor0; cO[jn][1] *= cor0;
            cO[jn][2] *= cor1; cO[jn][3] *= cor1;
        }
        rs0 += __shfl_xor_sync(0xffffffffu, rs0, 1);
        rs0 += __shfl_xor_sync(0xffffffffu, rs0, 2);
        rs1 += __shfl_xor_sync(0xffffffffu, rs1, 1);
        rs1 += __shfl_xor_sync(0xffffffffu, rs1, 2);
        l0 = l0 * cor0 + rs0;
        l1 = l1 * cor1 + rs1;
        m0 = mn0; m1 = mn1;

        __syncthreads();

        {
            int pr0 = (w * 16 + g) * FLD;
            int pr1 = (w * 16 + g + 8) * FLD;
#pragma unroll
            for (int jn = 0; jn < 8; jn++) {
                int pc = jn * 8 + 2 * t;
                sKP[pr0 + pc]     = f2tf(cS[jn][0]);
                sKP[pr0 + pc + 1] = f2tf(cS[jn][1]);
                sKP[pr1 + pc]     = f2tf(cS[jn][2]);
                sKP[pr1 + pc + 1] = f2tf(cS[jn][3]);
            }
        }
        __syncwarp();

        {
            int pr0 = (w * 16 + g) * FLD;
            int pr1 = (w * 16 + g + 8) * FLD;
#pragma unroll
            for (int kd = 0; kd < 8; kd++) {
                uint32_t aP[4];
                aP[0] = sKP[pr0 + kd * 8 + t];
                aP[1] = sKP[pr1 + kd * 8 + t];
                aP[2] = sKP[pr0 + kd * 8 + t + 4];
                aP[3] = sKP[pr1 + kd * 8 + t + 4];
#pragma unroll
                for (int jn = 0; jn < 8; jn++) {
                    uint32_t bV[2];
                    bV[0] = sV[(kd * 8 + t) * FLD + jn * 8 + g];
                    bV[1] = sV[(kd * 8 + t + 4) * FLD + jn * 8 + g];
                    mma8(cO[jn], aP, bV);
                }
            }
        }
    }

    if (m0 <= -9.9e8f) {
        l0 = (float)S_LEN;
#pragma unroll
        for (int jn = 0; jn < 8; jn++) {
            int d0 = hoff + jn * 8 + 2 * t;
            float s0 = 0.0f, s1 = 0.0f;
            for (int key = 0; key < S_LEN; key++) {
                const float* vp = V + (size_t)(bb * S_LEN + key) * DM + d0;
                s0 += vp[0]; s1 += vp[1];
            }
            cO[jn][0] = s0; cO[jn][1] = s1;
        }
    }
    if (m1 <= -9.9e8f) {
        l1 = (float)S_LEN;
#pragma unroll
        for (int jn = 0; jn < 8; jn++) {
            int d0 = hoff + jn * 8 + 2 * t;
            float s0 = 0.0f, s1 = 0.0f;
            for (int key = 0; key < S_LEN; key++) {
                const float* vp = V + (size_t)(bb * S_LEN + key) * DM + d0;
                s0 += vp[0]; s1 += vp[1];
            }
            cO[jn][2] = s0; cO[jn][3] = s1;
        }
    }

    // store O tf32-rounded: the O-projection consumes it via cp.async raw bits
    const float il0 = 1.0f / l0, il1 = 1.0f / l1;
    const size_t or0 = (qrowbase + g) * DM + hoff;
    const size_t or1 = (qrowbase + g + 8) * DM + hoff;
#pragma unroll
    for (int jn = 0; jn < 8; jn++) {
        int dc = jn * 8 + 2 * t;
        float2 v0 = make_float2(__uint_as_float(f2tf(cO[jn][0] * il0)),
                                __uint_as_float(f2tf(cO[jn][1] * il0)));
        float2 v1 = make_float2(__uint_as_float(f2tf(cO[jn][2] * il1)),
                                __uint_as_float(f2tf(cO[jn][3] * il1)));
        *(float2*)&O[or0 + dc] = v0;
        *(float2*)&O[or1 + dc] = v1;
    }
}

// ---------------------------------------------------------------------------
extern "C" void kernel_launch(void* const* d_in, const int* in_sizes, int n_in,
                              void* d_out, int out_size)
{
    const float* x   = (const float*)d_in[0];
    const int*   ids = (const int*)  d_in[1];
    const float* Wq  = (const float*)d_in[2];
    const float* bq  = (const float*)d_in[3];
    const float* Wk  = (const float*)d_in[4];
    const float* bk  = (const float*)d_in[5];
    const float* Wv  = (const float*)d_in[6];
    const float* bv  = (const float*)d_in[7];
    const float* Wo  = (const float*)d_in[8];
    const float* bo  = (const float*)d_in[9];
    float* out = (float*)d_out;

    float *Qp, *Kp, *Vp, *Op, *Xp, *WRp;
    cudaGetSymbolAddress((void**)&Qp, g_Q);
    cudaGetSymbolAddress((void**)&Kp, g_K);
    cudaGetSymbolAddress((void**)&Vp, g_V);
    cudaGetSymbolAddress((void**)&Op, g_O);
    cudaGetSymbolAddress((void**)&Xp, g_X);
    cudaGetSymbolAddress((void**)&WRp, g_WR);

    cudaFuncSetAttribute(flash_tc, cudaFuncAttributeMaxDynamicSharedMemorySize,
                         FLASH_SMEM_BYTES);
    cudaFuncSetAttribute(gemm_tf32, cudaFuncAttributeMaxDynamicSharedMemorySize,
                         GEMM_SMEM_BYTES);

    pad_kernel<<<1, 256>>>(ids);

    // tf32 pre-rounding of GEMM inputs
    const int XN4 = M_TOT * DM / 4, WN4 = DM * DM / 4;
    round_tf32<<<(XN4 + 255) / 256, 256>>>((const float4*)x, (float4*)Xp, XN4);
    round_tf32<<<(WN4 + 255) / 256, 256>>>((const float4*)Wq, (float4*)(WRp + 0 * DM * DM), WN4);
    round_tf32<<<(WN4 + 255) / 256, 256>>>((const float4*)Wk, (float4*)(WRp + 1 * DM * DM), WN4);
    round_tf32<<<(WN4 + 255) / 256, 256>>>((const float4*)Wv, (float4*)(WRp + 2 * DM * DM), WN4);
    round_tf32<<<(WN4 + 255) / 256, 256>>>((const float4*)Wo, (float4*)(WRp + 3 * DM * DM), WN4);

    dim3 gg(DM / 128, M_TOT / 128);   // (8, 32)
    gemm_tf32<<<gg, 256, GEMM_SMEM_BYTES>>>(Xp, WRp + 0 * DM * DM, bq, Qp, M_TOT, DM, DM);
    gemm_tf32<<<gg, 256, GEMM_SMEM_BYTES>>>(Xp, WRp + 1 * DM * DM, bk, Kp, M_TOT, DM, DM);
    gemm_tf32<<<gg, 256, GEMM_SMEM_BYTES>>>(Xp, WRp + 2 * DM * DM, bv, Vp, M_TOT, DM, DM);

    dim3 gf(S_LEN / 128, NH, BATCH);  // (16, 16, 2)
    flash_tc<<<gf, 256, FLASH_SMEM_BYTES>>>(Qp, Kp, Vp, Op);

    gemm_tf32<<<gg, 256, GEMM_SMEM_BYTES>>>(Op, WRp + 3 * DM * DM, bo, out, M_TOT, DM, DM);
}

// round 8
// speedup vs baseline: 1.5254x; 1.0669x over previous
#include <cuda_runtime.h>
#include <cstdint>

#define S_LEN 2048
#define DM    1024
#define NH    16
#define HD    64
#define BATCH 2
#define M_TOT (BATCH * S_LEN)   // 4096
#define XN4   (M_TOT * DM / 4)  // 1048576
#define WN4   (DM * DM / 4)     // 262144

// ---------------- scratch (device globals: no allocation allowed) ----------
__device__ float g_Q[M_TOT * DM];
__device__ float g_K[M_TOT * DM];
__device__ float g_V[M_TOT * DM];
__device__ float g_O[M_TOT * DM];
__device__ float g_X[M_TOT * DM];          // tf32-rounded x
__device__ float g_WR[4][DM * DM];         // tf32-rounded Wq,Wk,Wv,Wo
__device__ float g_pad[BATCH * S_LEN];     // 1.0f = padded (id==0), 0.0f = valid

// ---------------------------------------------------------------------------
__device__ __forceinline__ uint32_t f2tf(float f) {
    uint32_t u;
    asm("cvt.rna.tf32.f32 %0, %1;" : "=r"(u) : "f"(f));
    return u;
}

__device__ __forceinline__ void mma8(float* c, const uint32_t* a, const uint32_t* b) {
    asm volatile(
        "mma.sync.aligned.m16n8k8.row.col.f32.tf32.tf32.f32 "
        "{%0,%1,%2,%3},{%4,%5,%6,%7},{%8,%9},{%0,%1,%2,%3};"
        : "+f"(c[0]), "+f"(c[1]), "+f"(c[2]), "+f"(c[3])
        : "r"(a[0]), "r"(a[1]), "r"(a[2]), "r"(a[3]), "r"(b[0]), "r"(b[1]));
}

__device__ __forceinline__ void cpa16(uint32_t dst, const float* src) {
    asm volatile("cp.async.cg.shared.global [%0], [%1], 16;" :: "r"(dst), "l"(src));
}

// ---------------------------------------------------------------------------
// One-shot tf32 pre-rounding: x + Wq + Wk + Wv + Wo in a single launch.
// ---------------------------------------------------------------------------
__global__ void round_all(const float4* __restrict__ x,
                          const float4* __restrict__ wq, const float4* __restrict__ wk,
                          const float4* __restrict__ wv, const float4* __restrict__ wo,
                          float4* __restrict__ X, float4* __restrict__ WR)
{
    int i = blockIdx.x * blockDim.x + threadIdx.x;
    const float4* src;
    float4* dst;
    if (i < XN4) {
        src = x + i; dst = X + i;
    } else {
        int j = i - XN4;
        int w = j >> 18;              // / WN4
        int r = j & (WN4 - 1);
        src = (w == 0 ? wq : w == 1 ? wk : w == 2 ? wv : wo) + r;
        dst = WR + (size_t)w * WN4 + r;
    }
    float4 v = *src;
    float4 o;
    o.x = __uint_as_float(f2tf(v.x));
    o.y = __uint_as_float(f2tf(v.y));
    o.z = __uint_as_float(f2tf(v.z));
    o.w = __uint_as_float(f2tf(v.w));
    *dst = o;
}

// ---------------------------------------------------------------------------
// Pad-flag kernel with int32/int64 dtype sniffing (see R0 notes).
// ---------------------------------------------------------------------------
__global__ void pad_kernel(const int* __restrict__ ids)
{
    __shared__ int orv;
    if (threadIdx.x == 0) orv = 0;
    __syncthreads();
    int local = 0;
    for (int i = threadIdx.x; i < 2048; i += blockDim.x)
        local |= ids[2 * i + 1];
    atomicOr(&orv, local);
    __syncthreads();
    bool is64 = (orv == 0);
    for (int i = threadIdx.x; i < BATCH * S_LEN; i += blockDim.x) {
        int nz = is64 ? ((ids[2 * i] | ids[2 * i + 1]) != 0) : (ids[i] != 0);
        g_pad[i] = nz ? 0.0f : 1.0f;
    }
}

// ---------------------------------------------------------------------------
// TF32 tensor-core GEMM (NT), cp.async 3-stage pipeline, BK=32.
// Inputs MUST be tf32-rounded fp32; MMA reads raw bits.
// gridDim.z selects (W,bias,C) triple -> fused QKV in one launch.
// roundOut: store outputs tf32-rounded (for Q/K/V feeding flash).
// ---------------------------------------------------------------------------
#define GSTAGES 3
#define GSTAGE_WORDS (2 * 128 * 32)                       // A + B, 8192 words
#define GEMM_SMEM_BYTES (GSTAGES * GSTAGE_WORDS * 4)      // 96 KB

__global__ __launch_bounds__(256, 2)
void gemm_tf32(const float* __restrict__ A, const float* __restrict__ Wbase,
               const float* __restrict__ b0, const float* __restrict__ b1,
               const float* __restrict__ b2,
               float* __restrict__ C0, float* __restrict__ C1, float* __restrict__ C2,
               int roundOut)
{
    extern __shared__ uint32_t sm[];

    const int z = blockIdx.z;
    const float* W    = Wbase + (size_t)z * DM * DM;
    const float* bias = (z == 0) ? b0 : (z == 1) ? b1 : b2;
    float*       C    = (z == 0) ? C0 : (z == 1) ? C1 : C2;

    const int tid  = threadIdx.x;
    const int lane = tid & 31;
    const int wid  = tid >> 5;
    const int g    = lane >> 2;   // 0..7
    const int t    = lane & 3;    // 0..3
    const int warp_m = wid & 1;
    const int warp_n = wid >> 1;

    const int row0 = blockIdx.y * 128;
    const int col0 = blockIdx.x * 128;

    const int ldr  = tid >> 1;           // 0..127
    const int ldcb = (tid & 1) * 4;      // 0 or 4
    const float* Arow = A + (size_t)(row0 + ldr) * DM;
    const float* Wrow = W + (size_t)(col0 + ldr) * DM;
    uint32_t smbase = (uint32_t)__cvta_generic_to_shared((void*)sm);

    uint32_t adst[4], bdst[4];
#pragma unroll
    for (int cc = 0; cc < 4; cc++) {
        int c = ldcb + cc;
        uint32_t woff = (uint32_t)(ldr * 32 + ((c ^ (ldr & 7)) * 4));
        adst[cc] = smbase + woff * 4;
        bdst[cc] = smbase + (4096 + woff) * 4;
    }

    float c[4][4][4];
#pragma unroll
    for (int i = 0; i < 4; i++)
#pragma unroll
        for (int j = 0; j < 4; j++)
#pragma unroll
            for (int q = 0; q < 4; q++) c[i][j][q] = 0.0f;

    const int nIter = DM / 32;    // 32

#pragma unroll
    for (int s = 0; s < GSTAGES - 1; s++) {
        uint32_t soff = (uint32_t)(s * GSTAGE_WORDS * 4);
        int k0 = s * 32;
#pragma unroll
        for (int cc = 0; cc < 4; cc++) {
            int c4 = (ldcb + cc) * 4;
            cpa16(adst[cc] + soff, Arow + k0 + c4);
            cpa16(bdst[cc] + soff, Wrow + k0 + c4);
        }
        asm volatile("cp.async.commit_group;");
    }

    const int a_m0 = warp_m * 64 + g;
    const int b_n0 = warp_n * 32 + g;

    for (int it = 0; it < nIter; it++) {
        asm volatile("cp.async.wait_group 1;");
        __syncthreads();

        const uint32_t* As = sm + (it % GSTAGES) * GSTAGE_WORDS;
        const uint32_t* Bs = As + 4096;

#pragma unroll
        for (int sh = 0; sh < 4; sh++) {
            const int ch0 = ((2 * sh) ^ g) * 4 + t;
            const int ch1 = ((2 * sh + 1) ^ g) * 4 + t;
            uint32_t af[4][4];
            uint32_t bf[4][2];
#pragma unroll
            for (int i = 0; i < 4; i++) {
                int m = (a_m0 + i * 16) * 32;
                af[i][0] = As[m + ch0];
                af[i][1] = As[m + 256 + ch0];
                af[i][2] = As[m + ch1];
                af[i][3] = As[m + 256 + ch1];
            }
#pragma unroll
            for (int j = 0; j < 4; j++) {
                int n = (b_n0 + j * 8) * 32;
                bf[j][0] = Bs[n + ch0];
                bf[j][1] = Bs[n + ch1];
            }
#pragma unroll
            for (int i = 0; i < 4; i++)
#pragma unroll
                for (int j = 0; j < 4; j++)
                    mma8(c[i][j], af[i], bf[j]);
        }

        int nk = (it + GSTAGES - 1) * 32;
        if (nk < DM) {
            uint32_t soff = (uint32_t)(((it + GSTAGES - 1) % GSTAGES) * GSTAGE_WORDS * 4);
#pragma unroll
            for (int cc = 0; cc < 4; cc++) {
                int c4 = (ldcb + cc) * 4;
                cpa16(adst[cc] + soff, Arow + nk + c4);
                cpa16(bdst[cc] + soff, Wrow + nk + c4);
            }
        }
        asm volatile("cp.async.commit_group;");
    }

#pragma unroll
    for (int i = 0; i < 4; i++) {
        int rm = row0 + warp_m * 64 + i * 16 + g;
#pragma unroll
        for (int j = 0; j < 4; j++) {
            int cn = col0 + warp_n * 32 + j * 8 + 2 * t;
            float b0v = bias[cn], b1v = bias[cn + 1];
            float o00 = c[i][j][0] + b0v, o01 = c[i][j][1] + b1v;
            float o10 = c[i][j][2] + b0v, o11 = c[i][j][3] + b1v;
            if (roundOut) {
                o00 = __uint_as_float(f2tf(o00));
                o01 = __uint_as_float(f2tf(o01));
                o10 = __uint_as_float(f2tf(o10));
                o11 = __uint_as_float(f2tf(o11));
            }
            *(float2*)&C[(size_t)rm * DM + cn]       = make_float2(o00, o01);
            *(float2*)&C[(size_t)(rm + 8) * DM + cn] = make_float2(o10, o11);
        }
    }
}

// ---------------------------------------------------------------------------
// Flash attention v2 on tf32 tensor cores.
// Inputs Q/K/V are tf32-pre-rounded -> loaders move raw bits (no cvt).
// Dedicated P buffer -> 2 barriers per k-tile.
// Block: 256 threads (8 warps), 128-query tile; warp owns 16 rows.
// ---------------------------------------------------------------------------
#define FLD 72
#define FLASH_SMEM_BYTES ((128 * FLD + 64 * FLD + 64 * FLD) * 4 + 64 * 4)

__global__ __launch_bounds__(256)
void flash_tc(const float* __restrict__ Q, const float* __restrict__ K,
              const float* __restrict__ V, float* __restrict__ O)
{
    extern __shared__ uint32_t smem[];
    uint32_t* sP = smem;                        // Ps[row][key], 128 rows
    uint32_t* sK = smem + 128 * FLD;            // Ks[d][key] transposed, 64 rows
    uint32_t* sV = smem + 192 * FLD;            // Vs[key][d] raw, 64 rows
    float*    sPad = (float*)(smem + 256 * FLD);

    const int qt  = gridDim.x - 1 - blockIdx.x;   // biggest blocks first
    const int h   = blockIdx.y;
    const int bb  = blockIdx.z;
    const int tid = threadIdx.x;
    const int lane = tid & 31;
    const int w    = tid >> 5;   // warp 0..7
    const int g    = lane >> 2;  // 0..7
    const int t    = lane & 3;   // 0..3
    const int hoff = h * HD;

    const int qlow  = qt * 128 + w * 16 + g;
    const int qhigh = qlow + 8;
    const size_t qrowbase = (size_t)(bb * S_LEN + qt * 128 + w * 16);

    // Q fragments: pre-rounded; x0.125 (power of 2) keeps tf32-representable.
    uint32_t aQ[8][4];
#pragma unroll
    for (int kd = 0; kd < 8; kd++) {
        int cq = hoff + kd * 8 + t;
        aQ[kd][0] = __float_as_uint(Q[(qrowbase + g) * DM + cq] * 0.125f);
        aQ[kd][1] = __float_as_uint(Q[(qrowbase + g + 8) * DM + cq] * 0.125f);
        aQ[kd][2] = __float_as_uint(Q[(qrowbase + g) * DM + cq + 4] * 0.125f);
        aQ[kd][3] = __float_as_uint(Q[(qrowbase + g + 8) * DM + cq + 4] * 0.125f);
    }

    float m0 = -3.0e38f, m1 = -3.0e38f, l0 = 0.0f, l1 = 0.0f;
    float cO[8][4];
#pragma unroll
    for (int j = 0; j < 8; j++)
#pragma unroll
        for (int q = 0; q < 4; q++) cO[j][q] = 0.0f;

    const int ntiles = 2 * qt + 2;
    for (int kt = 0; kt < ntiles; kt++) {
        const int kbase = bb * S_LEN + kt * 64;
        __syncthreads();   // prior tile's K/V fully consumed
        // K tile: transposed scatter, raw bits
#pragma unroll
        for (int it = 0; it < 4; it++) {
            int linear = it * 256 + tid;
            int key = linear & 63;
            int dq  = linear >> 6;
            float4 kv = *(const float4*)&K[(size_t)(kbase + key) * DM + hoff + dq * 4];
            sK[(dq * 4 + 0) * FLD + key] = __float_as_uint(kv.x);
            sK[(dq * 4 + 1) * FLD + key] = __float_as_uint(kv.y);
            sK[(dq * 4 + 2) * FLD + key] = __float_as_uint(kv.z);
            sK[(dq * 4 + 3) * FLD + key] = __float_as_uint(kv.w);
        }
        // V tile: raw layout, vector copy
#pragma unroll
        for (int it = 0; it < 4; it++) {
            int linear = it * 256 + tid;
            int key = linear >> 4;
            int dq  = linear & 15;
            uint4 vv = *(const uint4*)&V[(size_t)(kbase + key) * DM + hoff + dq * 4];
            *(uint4*)&sV[key * FLD + dq * 4] = vv;
        }
        if (tid < 64) sPad[tid] = g_pad[kbase + tid];
        __syncthreads();

        // S = (Q/8) K^T
        float cS[8][4];
#pragma unroll
        for (int jn = 0; jn < 8; jn++) {
            cS[jn][0] = cS[jn][1] = cS[jn][2] = cS[jn][3] = 0.0f;
#pragma unroll
            for (int kd = 0; kd < 8; kd++) {
                uint32_t bK[2];
                bK[0] = sK[(kd * 8 + t) * FLD + jn * 8 + g];
                bK[1] = sK[(kd * 8 + t + 4) * FLD + jn * 8 + g];
                mma8(cS[jn], aQ[kd], bK);
            }
        }

        // mask (causal + pad); masked -> exactly -1e9
        float mx0 = -3.0e38f, mx1 = -3.0e38f;
#pragma unroll
        for (int jn = 0; jn < 8; jn++) {
            int col = jn * 8 + 2 * t;
            int k0g = kt * 64 + col;
            bool p0 = (sPad[col] == 0.0f);
            bool p1 = (sPad[col + 1] == 0.0f);
            cS[jn][0] = (k0g     <= qlow  && p0) ? cS[jn][0] : -1.0e9f;
            cS[jn][1] = (k0g + 1 <= qlow  && p1) ? cS[jn][1] : -1.0e9f;
            cS[jn][2] = (k0g     <= qhigh && p0) ? cS[jn][2] : -1.0e9f;
            cS[jn][3] = (k0g + 1 <= qhigh && p1) ? cS[jn][3] : -1.0e9f;
            mx0 = fmaxf(mx0, fmaxf(cS[jn][0], cS[jn][1]));
            mx1 = fmaxf(mx1, fmaxf(cS[jn][2], cS[jn][3]));
        }
        mx0 = fmaxf(mx0, __shfl_xor_sync(0xffffffffu, mx0, 1));
        mx0 = fmaxf(mx0, __shfl_xor_sync(0xffffffffu, mx0, 2));
        mx1 = fmaxf(mx1, __shfl_xor_sync(0xffffffffu, mx1, 1));
        mx1 = fmaxf(mx1, __shfl_xor_sync(0xffffffffu, mx1, 2));

        float mn0 = fmaxf(m0, mx0), mn1 = fmaxf(m1, mx1);
        float cor0 = __expf(m0 - mn0), cor1 = __expf(m1 - mn1);

        float rs0 = 0.0f, rs1 = 0.0f;
#pragma unroll
        for (int jn = 0; jn < 8; jn++) {
            cS[jn][0] = __expf(cS[jn][0] - mn0);
            cS[jn][1] = __expf(cS[jn][1] - mn0);
            cS[jn][2] = __expf(cS[jn][2] - mn1);
            cS[jn][3] = __expf(cS[jn][3] - mn1);
            rs0 += cS[jn][0] + cS[jn][1];
            rs1 += cS[jn][2] + cS[jn][3];
            cO[jn][0] *= cor0; cO[jn][1] *= cor0;
            cO[jn][2] *= cor1; cO[jn][3] *= cor1;
        }
        rs0 += __shfl_xor_sync(0xffffffffu, rs0, 1);
        rs0 += __shfl_xor_sync(0xffffffffu, rs0, 2);
        rs1 += __shfl_xor_sync(0xffffffffu, rs1, 1);
        rs1 += __shfl_xor_sync(0xffffffffu, rs1, 2);
        l0 = l0 * cor0 + rs0;
        l1 = l1 * cor1 + rs1;
        m0 = mn0; m1 = mn1;

        // P -> dedicated smem buffer (no block barrier needed)
        {
            int pr0 = (w * 16 + g) * FLD;
            int pr1 = (w * 16 + g + 8) * FLD;
#pragma unroll
            for (int jn = 0; jn < 8; jn++) {
                int pc = jn * 8 + 2 * t;
                sP[pr0 + pc]     = f2tf(cS[jn][0]);
                sP[pr0 + pc + 1] = f2tf(cS[jn][1]);
                sP[pr1 + pc]     = f2tf(cS[jn][2]);
                sP[pr1 + pc + 1] = f2tf(cS[jn][3]);
            }
        }
        __syncwarp();

        // O += P V
        {
            int pr0 = (w * 16 + g) * FLD;
            int pr1 = (w * 16 + g + 8) * FLD;
#pragma unroll
            for (int kd = 0; kd < 8; kd++) {
                uint32_t aP[4];
                aP[0] = sP[pr0 + kd * 8 + t];
                aP[1] = sP[pr1 + kd * 8 + t];
                aP[2] = sP[pr0 + kd * 8 + t + 4];
                aP[3] = sP[pr1 + kd * 8 + t + 4];
#pragma unroll
                for (int jn = 0; jn < 8; jn++) {
                    uint32_t bV[2];
                    bV[0] = sV[(kd * 8 + t) * FLD + jn * 8 + g];
                    bV[1] = sV[(kd * 8 + t + 4) * FLD + jn * 8 + g];
                    mma8(cO[jn], aP, bV);
                }
            }
        }
    }

    // Degenerate rows (entire causal prefix padded): uniform over ALL keys.
    if (m0 <= -9.9e8f) {
        l0 = (float)S_LEN;
#pragma unroll
        for (int jn = 0; jn < 8; jn++) {
            int d0 = hoff + jn * 8 + 2 * t;
            float s0 = 0.0f, s1 = 0.0f;
            for (int key = 0; key < S_LEN; key++) {
                const float* vp = V + (size_t)(bb * S_LEN + key) * DM + d0;
                s0 += vp[0]; s1 += vp[1];
            }
            cO[jn][0] = s0; cO[jn][1] = s1;
        }
    }
    if (m1 <= -9.9e8f) {
        l1 = (float)S_LEN;
#pragma unroll
        for (int jn = 0; jn < 8; jn++) {
            int d0 = hoff + jn * 8 + 2 * t;
            float s0 = 0.0f, s1 = 0.0f;
            for (int key = 0; key < S_LEN; key++) {
                const float* vp = V + (size_t)(bb * S_LEN + key) * DM + d0;
                s0 += vp[0]; s1 += vp[1];
            }
            cO[jn][2] = s0; cO[jn][3] = s1;
        }
    }

    // store O tf32-rounded: O-projection consumes raw bits via cp.async
    const float il0 = 1.0f / l0, il1 = 1.0f / l1;
    const size_t or0 = (qrowbase + g) * DM + hoff;
    const size_t or1 = (qrowbase + g + 8) * DM + hoff;
#pragma unroll
    for (int jn = 0; jn < 8; jn++) {
        int dc = jn * 8 + 2 * t;
        float2 v0 = make_float2(__uint_as_float(f2tf(cO[jn][0] * il0)),
                                __uint_as_float(f2tf(cO[jn][1] * il0)));
        float2 v1 = make_float2(__uint_as_float(f2tf(cO[jn][2] * il1)),
                                __uint_as_float(f2tf(cO[jn][3] * il1)));
        *(float2*)&O[or0 + dc] = v0;
        *(float2*)&O[or1 + dc] = v1;
    }
}

// ---------------------------------------------------------------------------
extern "C" void kernel_launch(void* const* d_in, const int* in_sizes, int n_in,
                              void* d_out, int out_size)
{
    const float* x   = (const float*)d_in[0];
    const int*   ids = (const int*)  d_in[1];
    const float* Wq  = (const float*)d_in[2];
    const float* bq  = (const float*)d_in[3];
    const float* Wk  = (const float*)d_in[4];
    const float* bk  = (const float*)d_in[5];
    const float* Wv  = (const float*)d_in[6];
    const float* bv  = (const float*)d_in[7];
    const float* Wo  = (const float*)d_in[8];
    const float* bo  = (const float*)d_in[9];
    float* out = (float*)d_out;

    float *Qp, *Kp, *Vp, *Op, *Xp, *WRp;
    cudaGetSymbolAddress((void**)&Qp, g_Q);
    cudaGetSymbolAddress((void**)&Kp, g_K);
    cudaGetSymbolAddress((void**)&Vp, g_V);
    cudaGetSymbolAddress((void**)&Op, g_O);
    cudaGetSymbolAddress((void**)&Xp, g_X);
    cudaGetSymbolAddress((void**)&WRp, g_WR);

    cudaFuncSetAttribute(flash_tc, cudaFuncAttributeMaxDynamicSharedMemorySize,
                         FLASH_SMEM_BYTES);
    cudaFuncSetAttribute(gemm_tf32, cudaFuncAttributeMaxDynamicSharedMemorySize,
                         GEMM_SMEM_BYTES);

    pad_kernel<<<1, 256>>>(ids);

    const int TOT4 = XN4 + 4 * WN4;   // 2097152
    round_all<<<TOT4 / 256, 256>>>((const float4*)x, (const float4*)Wq,
                                   (const float4*)Wk, (const float4*)Wv,
                                   (const float4*)Wo, (float4*)Xp, (float4*)WRp);

    // fused QKV projections (z selects W/bias/C), outputs tf32-rounded
    dim3 gqkv(DM / 128, M_TOT / 128, 3);   // (8, 32, 3)
    gemm_tf32<<<gqkv, 256, GEMM_SMEM_BYTES>>>(Xp, WRp, bq, bk, bv, Qp, Kp, Vp, 1);

    dim3 gf(S_LEN / 128, NH, BATCH);       // (16, 16, 2)
    flash_tc<<<gf, 256, FLASH_SMEM_BYTES>>>(Qp, Kp, Vp, Op);

    // output projection, unrounded
    dim3 go(DM / 128, M_TOT / 128, 1);
    gemm_tf32<<<go, 256, GEMM_SMEM_BYTES>>>(Op, WRp + 3 * (size_t)DM * DM,
                                            bo, bo, bo, out, out, out, 0);
}

// round 9
// speedup vs baseline: 1.7657x; 1.1576x over previous
#include <cuda_runtime.h>
#include <cstdint>

#define S_LEN 2048
#define DM    1024
#define NH    16
#define HD    64
#define BATCH 2
#define M_TOT (BATCH * S_LEN)   // 4096
#define XN4   (M_TOT * DM / 4)  // 1048576
#define WN4   (DM * DM / 4)     // 262144

// ---------------- scratch (device globals: no allocation allowed) ----------
__device__ float g_Q[M_TOT * DM];
__device__ float g_K[M_TOT * DM];
__device__ float g_V[M_TOT * DM];
__device__ float g_O[M_TOT * DM];
__device__ float g_X[M_TOT * DM];          // tf32-rounded x
__device__ float g_WR[4][DM * DM];         // tf32-rounded Wq,Wk,Wv,Wo
__device__ float g_pad[BATCH * S_LEN];     // 1.0f = padded (id==0), 0.0f = valid

// ---------------------------------------------------------------------------
__device__ __forceinline__ uint32_t f2tf(float f) {
    uint32_t u;
    asm("cvt.rna.tf32.f32 %0, %1;" : "=r"(u) : "f"(f));
    return u;
}

__device__ __forceinline__ void mma8(float* c, const uint32_t* a, const uint32_t* b) {
    asm volatile(
        "mma.sync.aligned.m16n8k8.row.col.f32.tf32.tf32.f32 "
        "{%0,%1,%2,%3},{%4,%5,%6,%7},{%8,%9},{%0,%1,%2,%3};"
        : "+f"(c[0]), "+f"(c[1]), "+f"(c[2]), "+f"(c[3])
        : "r"(a[0]), "r"(a[1]), "r"(a[2]), "r"(a[3]), "r"(b[0]), "r"(b[1]));
}

__device__ __forceinline__ void cpa16(uint32_t dst, const float* src) {
    asm volatile("cp.async.cg.shared.global [%0], [%1], 16;" :: "r"(dst), "l"(src));
}

// ---------------------------------------------------------------------------
// One-shot tf32 pre-rounding: x + Wq + Wk + Wv + Wo in a single launch.
// ---------------------------------------------------------------------------
__global__ void round_all(const float4* __restrict__ x,
                          const float4* __restrict__ wq, const float4* __restrict__ wk,
                          const float4* __restrict__ wv, const float4* __restrict__ wo,
                          float4* __restrict__ X, float4* __restrict__ WR)
{
    int i = blockIdx.x * blockDim.x + threadIdx.x;
    const float4* src;
    float4* dst;
    if (i < XN4) {
        src = x + i; dst = X + i;
    } else {
        int j = i - XN4;
        int w = j >> 18;              // / WN4
        int r = j & (WN4 - 1);
        src = (w == 0 ? wq : w == 1 ? wk : w == 2 ? wv : wo) + r;
        dst = WR + (size_t)w * WN4 + r;
    }
    float4 v = *src;
    float4 o;
    o.x = __uint_as_float(f2tf(v.x));
    o.y = __uint_as_float(f2tf(v.y));
    o.z = __uint_as_float(f2tf(v.z));
    o.w = __uint_as_float(f2tf(v.w));
    *dst = o;
}

// ---------------------------------------------------------------------------
// Pad-flag kernel with int32/int64 dtype sniffing (see R0 notes).
// ---------------------------------------------------------------------------
__global__ void pad_kernel(const int* __restrict__ ids)
{
    __shared__ int orv;
    if (threadIdx.x == 0) orv = 0;
    __syncthreads();
    int local = 0;
    for (int i = threadIdx.x; i < 2048; i += blockDim.x)
        local |= ids[2 * i + 1];
    atomicOr(&orv, local);
    __syncthreads();
    bool is64 = (orv == 0);
    for (int i = threadIdx.x; i < BATCH * S_LEN; i += blockDim.x) {
        int nz = is64 ? ((ids[2 * i] | ids[2 * i + 1]) != 0) : (ids[i] != 0);
        g_pad[i] = nz ? 0.0f : 1.0f;
    }
}

// ---------------------------------------------------------------------------
// TF32 tensor-core GEMM (NT), cp.async 3-stage pipeline, BK=32. (R8, passing)
// ---------------------------------------------------------------------------
#define GSTAGES 3
#define GSTAGE_WORDS (2 * 128 * 32)
#define GEMM_SMEM_BYTES (GSTAGES * GSTAGE_WORDS * 4)      // 96 KB

__global__ __launch_bounds__(256, 2)
void gemm_tf32(const float* __restrict__ A, const float* __restrict__ Wbase,
               const float* __restrict__ b0, const float* __restrict__ b1,
               const float* __restrict__ b2,
               float* __restrict__ C0, float* __restrict__ C1, float* __restrict__ C2,
               int roundOut)
{
    extern __shared__ uint32_t sm[];

    const int z = blockIdx.z;
    const float* W    = Wbase + (size_t)z * DM * DM;
    const float* bias = (z == 0) ? b0 : (z == 1) ? b1 : b2;
    float*       C    = (z == 0) ? C0 : (z == 1) ? C1 : C2;

    const int tid  = threadIdx.x;
    const int lane = tid & 31;
    const int wid  = tid >> 5;
    const int g    = lane >> 2;
    const int t    = lane & 3;
    const int warp_m = wid & 1;
    const int warp_n = wid >> 1;

    const int row0 = blockIdx.y * 128;
    const int col0 = blockIdx.x * 128;

    const int ldr  = tid >> 1;
    const int ldcb = (tid & 1) * 4;
    const float* Arow = A + (size_t)(row0 + ldr) * DM;
    const float* Wrow = W + (size_t)(col0 + ldr) * DM;
    uint32_t smbase = (uint32_t)__cvta_generic_to_shared((void*)sm);

    uint32_t adst[4], bdst[4];
#pragma unroll
    for (int cc = 0; cc < 4; cc++) {
        int c = ldcb + cc;
        uint32_t woff = (uint32_t)(ldr * 32 + ((c ^ (ldr & 7)) * 4));
        adst[cc] = smbase + woff * 4;
        bdst[cc] = smbase + (4096 + woff) * 4;
    }

    float c[4][4][4];
#pragma unroll
    for (int i = 0; i < 4; i++)
#pragma unroll
        for (int j = 0; j < 4; j++)
#pragma unroll
            for (int q = 0; q < 4; q++) c[i][j][q] = 0.0f;

    const int nIter = DM / 32;

#pragma unroll
    for (int s = 0; s < GSTAGES - 1; s++) {
        uint32_t soff = (uint32_t)(s * GSTAGE_WORDS * 4);
        int k0 = s * 32;
#pragma unroll
        for (int cc = 0; cc < 4; cc++) {
            int c4 = (ldcb + cc) * 4;
            cpa16(adst[cc] + soff, Arow + k0 + c4);
            cpa16(bdst[cc] + soff, Wrow + k0 + c4);
        }
        asm volatile("cp.async.commit_group;");
    }

    const int a_m0 = warp_m * 64 + g;
    const int b_n0 = warp_n * 32 + g;

    for (int it = 0; it < nIter; it++) {
        asm volatile("cp.async.wait_group 1;");
        __syncthreads();

        const uint32_t* As = sm + (it % GSTAGES) * GSTAGE_WORDS;
        const uint32_t* Bs = As + 4096;

#pragma unroll
        for (int sh = 0; sh < 4; sh++) {
            const int ch0 = ((2 * sh) ^ g) * 4 + t;
            const int ch1 = ((2 * sh + 1) ^ g) * 4 + t;
            uint32_t af[4][4];
            uint32_t bf[4][2];
#pragma unroll
            for (int i = 0; i < 4; i++) {
                int m = (a_m0 + i * 16) * 32;
                af[i][0] = As[m + ch0];
                af[i][1] = As[m + 256 + ch0];
                af[i][2] = As[m + ch1];
                af[i][3] = As[m + 256 + ch1];
            }
#pragma unroll
            for (int j = 0; j < 4; j++) {
                int n = (b_n0 + j * 8) * 32;
                bf[j][0] = Bs[n + ch0];
                bf[j][1] = Bs[n + ch1];
            }
#pragma unroll
            for (int i = 0; i < 4; i++)
#pragma unroll
                for (int j = 0; j < 4; j++)
                    mma8(c[i][j], af[i], bf[j]);
        }

        int nk = (it + GSTAGES - 1) * 32;
        if (nk < DM) {
            uint32_t soff = (uint32_t)(((it + GSTAGES - 1) % GSTAGES) * GSTAGE_WORDS * 4);
#pragma unroll
            for (int cc = 0; cc < 4; cc++) {
                int c4 = (ldcb + cc) * 4;
                cpa16(adst[cc] + soff, Arow + nk + c4);
                cpa16(bdst[cc] + soff, Wrow + nk + c4);
            }
        }
        asm volatile("cp.async.commit_group;");
    }

#pragma unroll
    for (int i = 0; i < 4; i++) {
        int rm = row0 + warp_m * 64 + i * 16 + g;
#pragma unroll
        for (int j = 0; j < 4; j++) {
            int cn = col0 + warp_n * 32 + j * 8 + 2 * t;
            float b0v = bias[cn], b1v = bias[cn + 1];
            float o00 = c[i][j][0] + b0v, o01 = c[i][j][1] + b1v;
            float o10 = c[i][j][2] + b0v, o11 = c[i][j][3] + b1v;
            if (roundOut) {
                o00 = __uint_as_float(f2tf(o00));
                o01 = __uint_as_float(f2tf(o01));
                o10 = __uint_as_float(f2tf(o10));
                o11 = __uint_as_float(f2tf(o11));
            }
            *(float2*)&C[(size_t)rm * DM + cn]       = make_float2(o00, o01);
            *(float2*)&C[(size_t)(rm + 8) * DM + cn] = make_float2(o10, o11);
        }
    }
}

// ---------------------------------------------------------------------------
// Flash attention v2, tf32 tensor cores, cp.async double-buffered K/V,
// causal-paired q-tiles (uniform 34 k-tiles/block), 256 blocks = 1 wave.
// K stored [key][d] directly (no transpose); Q/K/V pre-rounded tf32.
// ---------------------------------------------------------------------------
#define FLD 72
#define KV_WORDS (64 * FLD)
#define FLASH_SMEM_BYTES ((128 * FLD + 4 * KV_WORDS + 128) * 4)   // 111104

__global__ __launch_bounds__(256)
void flash_tc(const float* __restrict__ Q, const float* __restrict__ K,
              const float* __restrict__ V, float* __restrict__ O)
{
    extern __shared__ uint32_t smem[];
    uint32_t* sP  = smem;                             // Ps[row][key], 128 rows
    uint32_t* sKb = smem + 128 * FLD;                 // K bufs: 2 x 64 rows
    uint32_t* sVb = smem + 128 * FLD + 2 * KV_WORDS;  // V bufs: 2 x 64 rows
    float*    sPad = (float*)(smem + 128 * FLD + 4 * KV_WORDS);  // 2 x 64

    const int qx  = blockIdx.x;                  // 0..7
    const int h   = blockIdx.y;
    const int bb  = blockIdx.z;
    const int tid = threadIdx.x;
    const int lane = tid & 31;
    const int w    = tid >> 5;
    const int g    = lane >> 2;
    const int t    = lane & 3;
    const int hoff = h * HD;

    // cp.async loader mapping: 4 iters x (row = linear>>4, chunk = linear&15)
    int ld_row[4], ld_c4[4];
    uint32_t kdst[4], vdst[4];
    {
        uint32_t smb = (uint32_t)__cvta_generic_to_shared((void*)smem);
        uint32_t kb = smb + (128 * FLD) * 4;
        uint32_t vb = smb + (128 * FLD + 2 * KV_WORDS) * 4;
#pragma unroll
        for (int it = 0; it < 4; it++) {
            int linear = it * 256 + tid;
            ld_row[it] = linear >> 4;
            ld_c4[it]  = (linear & 15) * 4;
            uint32_t off = (uint32_t)(ld_row[it] * FLD + ld_c4[it]) * 4;
            kdst[it] = kb + off;
            vdst[it] = vb + off;
        }
    }

#pragma unroll 1
    for (int sub = 0; sub < 2; sub++) {
        const int qt = (sub == 0) ? qx : (15 - qx);
        const int qlow  = qt * 128 + w * 16 + g;
        const int qhigh = qlow + 8;
        const size_t qrowbase = (size_t)(bb * S_LEN + qt * 128 + w * 16);
        const int ntiles = 2 * qt + 2;

        // Q fragments (pre-rounded; x0.125 exact)
        uint32_t aQ[8][4];
#pragma unroll
        for (int kd = 0; kd < 8; kd++) {
            int cq = hoff + kd * 8 + t;
            aQ[kd][0] = __float_as_uint(Q[(qrowbase + g) * DM + cq] * 0.125f);
            aQ[kd][1] = __float_as_uint(Q[(qrowbase + g + 8) * DM + cq] * 0.125f);
            aQ[kd][2] = __float_as_uint(Q[(qrowbase + g) * DM + cq + 4] * 0.125f);
            aQ[kd][3] = __float_as_uint(Q[(qrowbase + g + 8) * DM + cq + 4] * 0.125f);
        }

        float m0 = -3.0e38f, m1 = -3.0e38f, l0 = 0.0f, l1 = 0.0f;
        float cO[8][4];
#pragma unroll
        for (int j = 0; j < 8; j++)
#pragma unroll
            for (int q = 0; q < 4; q++) cO[j][q] = 0.0f;

        __syncthreads();   // prior q-tile fully consumed before buffer reuse

        // prologue: prefetch tile 0 -> buf 0
        {
            const int kbase = bb * S_LEN;  // kt=0 (qt>=0 so tile 0 exists)
            const int kb2 = kbase + qt * 0;  // silence unused warning path
            (void)kb2;
#pragma unroll
            for (int it = 0; it < 4; it++) {
                const float* ksrc = &K[(size_t)(kbase + ld_row[it]) * DM + hoff + ld_c4[it]];
                const float* vsrc = &V[(size_t)(kbase + ld_row[it]) * DM + hoff + ld_c4[it]];
                cpa16(kdst[it], ksrc);
                cpa16(vdst[it], vsrc);
            }
            if (tid < 64) sPad[tid] = g_pad[kbase + tid];
            asm volatile("cp.async.commit_group;");
        }

        for (int kt = 0; kt < ntiles; kt++) {
            asm volatile("cp.async.wait_group 0;");
            __syncthreads();

            // prefetch next tile into other buffer
            if (kt + 1 < ntiles) {
                const int nb = (kt + 1) & 1;
                const int kbase = bb * S_LEN + (kt + 1) * 64;
                const uint32_t boff = (uint32_t)(nb * KV_WORDS * 4);
#pragma unroll
                for (int it = 0; it < 4; it++) {
                    const float* ksrc = &K[(size_t)(kbase + ld_row[it]) * DM + hoff + ld_c4[it]];
                    const float* vsrc = &V[(size_t)(kbase + ld_row[it]) * DM + hoff + ld_c4[it]];
                    cpa16(kdst[it] + boff, ksrc);
                    cpa16(vdst[it] + boff, vsrc);
                }
                if (tid < 64) sPad[nb * 64 + tid] = g_pad[kbase + tid];
            }
            asm volatile("cp.async.commit_group;");

            const int buf = kt & 1;
            const uint32_t* sK = sKb + buf * KV_WORDS;
            const uint32_t* sV = sVb + buf * KV_WORDS;
            const float*    pad = sPad + buf * 64;

            // S = (Q/8) K^T  (K read as B[n=key][k=d] from [key][d] layout)
            float cS[8][4];
#pragma unroll
            for (int jn = 0; jn < 8; jn++) {
                cS[jn][0] = cS[jn][1] = cS[jn][2] = cS[jn][3] = 0.0f;
                const uint32_t* krow = sK + (jn * 8 + g) * FLD;
#pragma unroll
                for (int kd = 0; kd < 8; kd++) {
                    uint32_t bK[2];
                    bK[0] = krow[kd * 8 + t];
                    bK[1] = krow[kd * 8 + t + 4];
                    mma8(cS[jn], aQ[kd], bK);
                }
            }

            // mask (causal + pad); masked -> exactly -1e9
            float mx0 = -3.0e38f, mx1 = -3.0e38f;
#pragma unroll
            for (int jn = 0; jn < 8; jn++) {
                int col = jn * 8 + 2 * t;
                int k0g = kt * 64 + col;
                bool p0 = (pad[col] == 0.0f);
                bool p1 = (pad[col + 1] == 0.0f);
                cS[jn][0] = (k0g     <= qlow  && p0) ? cS[jn][0] : -1.0e9f;
                cS[jn][1] = (k0g + 1 <= qlow  && p1) ? cS[jn][1] : -1.0e9f;
                cS[jn][2] = (k0g     <= qhigh && p0) ? cS[jn][2] : -1.0e9f;
                cS[jn][3] = (k0g + 1 <= qhigh && p1) ? cS[jn][3] : -1.0e9f;
                mx0 = fmaxf(mx0, fmaxf(cS[jn][0], cS[jn][1]));
                mx1 = fmaxf(mx1, fmaxf(cS[jn][2], cS[jn][3]));
            }
            mx0 = fmaxf(mx0, __shfl_xor_sync(0xffffffffu, mx0, 1));
            mx0 = fmaxf(mx0, __shfl_xor_sync(0xffffffffu, mx0, 2));
            mx1 = fmaxf(mx1, __shfl_xor_sync(0xffffffffu, mx1, 1));
            mx1 = fmaxf(mx1, __shfl_xor_sync(0xffffffffu, mx1, 2));

            float mn0 = fmaxf(m0, mx0), mn1 = fmaxf(m1, mx1);
            float cor0 = __expf(m0 - mn0), cor1 = __expf(m1 - mn1);

            float rs0 = 0.0f, rs1 = 0.0f;
#pragma unroll
            for (int jn = 0; jn < 8; jn++) {
                cS[jn][0] = __expf(cS[jn][0] - mn0);
                cS[jn][1] = __expf(cS[jn][1] - mn0);
                cS[jn][2] = __expf(cS[jn][2] - mn1);
                cS[jn][3] = __expf(cS[jn][3] - mn1);
                rs0 += cS[jn][0] + cS[jn][1];
                rs1 += cS[jn][2] + cS[jn][3];
                cO[jn][0] *= cor0; cO[jn][1] *= cor0;
                cO[jn][2] *= cor1; cO[jn][3] *= cor1;
            }
            rs0 += __shfl_xor_sync(0xffffffffu, rs0, 1);
            rs0 += __shfl_xor_sync(0xffffffffu, rs0, 2);
            rs1 += __shfl_xor_sync(0xffffffffu, rs1, 1);
            rs1 += __shfl_xor_sync(0xffffffffu, rs1, 2);
            l0 = l0 * cor0 + rs0;
            l1 = l1 * cor1 + rs1;
            m0 = mn0; m1 = mn1;

            // P -> per-warp region of sP (warp-private: syncwarp suffices)
            {
                int pr0 = (w * 16 + g) * FLD;
                int pr1 = (w * 16 + g + 8) * FLD;
#pragma unroll
                for (int jn = 0; jn < 8; jn++) {
                    int pc = jn * 8 + 2 * t;
                    sP[pr0 + pc]     = f2tf(cS[jn][0]);
                    sP[pr0 + pc + 1] = f2tf(cS[jn][1]);
                    sP[pr1 + pc]     = f2tf(cS[jn][2]);
                    sP[pr1 + pc + 1] = f2tf(cS[jn][3]);
                }
            }
            __syncwarp();

            // O += P V
            {
                int pr0 = (w * 16 + g) * FLD;
                int pr1 = (w * 16 + g + 8) * FLD;
#pragma unroll
                for (int kd = 0; kd < 8; kd++) {
                    uint32_t aP[4];
                    aP[0] = sP[pr0 + kd * 8 + t];
                    aP[1] = sP[pr1 + kd * 8 + t];
                    aP[2] = sP[pr0 + kd * 8 + t + 4];
                    aP[3] = sP[pr1 + kd * 8 + t + 4];
#pragma unroll
                    for (int jn = 0; jn < 8; jn++) {
                        uint32_t bV[2];
                        bV[0] = sV[(kd * 8 + t) * FLD + jn * 8 + g];
                        bV[1] = sV[(kd * 8 + t + 4) * FLD + jn * 8 + g];
                        mma8(cO[jn], aP, bV);
                    }
                }
            }
        }

        // Degenerate rows (entire causal prefix padded): uniform over ALL keys.
        if (m0 <= -9.9e8f) {
            l0 = (float)S_LEN;
#pragma unroll
            for (int jn = 0; jn < 8; jn++) {
                int d0 = hoff + jn * 8 + 2 * t;
                float s0 = 0.0f, s1 = 0.0f;
                for (int key = 0; key < S_LEN; key++) {
                    const float* vp = V + (size_t)(bb * S_LEN + key) * DM + d0;
                    s0 += vp[0]; s1 += vp[1];
                }
                cO[jn][0] = s0; cO[jn][1] = s1;
            }
        }
        if (m1 <= -9.9e8f) {
            l1 = (float)S_LEN;
#pragma unroll
            for (int jn = 0; jn < 8; jn++) {
                int d0 = hoff + jn * 8 + 2 * t;
                float s0 = 0.0f, s1 = 0.0f;
                for (int key = 0; key < S_LEN; key++) {
                    const float* vp = V + (size_t)(bb * S_LEN + key) * DM + d0;
                    s0 += vp[0]; s1 += vp[1];
                }
                cO[jn][2] = s0; cO[jn][3] = s1;
            }
        }

        // store O tf32-rounded (O-projection consumes raw bits via cp.async)
        const float il0 = 1.0f / l0, il1 = 1.0f / l1;
        const size_t or0 = (qrowbase + g) * DM + hoff;
        const size_t or1 = (qrowbase + g + 8) * DM + hoff;
#pragma unroll
        for (int jn = 0; jn < 8; jn++) {
            int dc = jn * 8 + 2 * t;
            float2 v0 = make_float2(__uint_as_float(f2tf(cO[jn][0] * il0)),
                                    __uint_as_float(f2tf(cO[jn][1] * il0)));
            float2 v1 = make_float2(__uint_as_float(f2tf(cO[jn][2] * il1)),
                                    __uint_as_float(f2tf(cO[jn][3] * il1)));
            *(float2*)&O[or0 + dc] = v0;
            *(float2*)&O[or1 + dc] = v1;
        }
    }
}

// ---------------------------------------------------------------------------
extern "C" void kernel_launch(void* const* d_in, const int* in_sizes, int n_in,
                              void* d_out, int out_size)
{
    const float* x   = (const float*)d_in[0];
    const int*   ids = (const int*)  d_in[1];
    const float* Wq  = (const float*)d_in[2];
    const float* bq  = (const float*)d_in[3];
    const float* Wk  = (const float*)d_in[4];
    const float* bk  = (const float*)d_in[5];
    const float* Wv  = (const float*)d_in[6];
    const float* bv  = (const float*)d_in[7];
    const float* Wo  = (const float*)d_in[8];
    const float* bo  = (const float*)d_in[9];
    float* out = (float*)d_out;

    float *Qp, *Kp, *Vp, *Op, *Xp, *WRp;
    cudaGetSymbolAddress((void**)&Qp, g_Q);
    cudaGetSymbolAddress((void**)&Kp, g_K);
    cudaGetSymbolAddress((void**)&Vp, g_V);
    cudaGetSymbolAddress((void**)&Op, g_O);
    cudaGetSymbolAddress((void**)&Xp, g_X);
    cudaGetSymbolAddress((void**)&WRp, g_WR);

    cudaFuncSetAttribute(flash_tc, cudaFuncAttributeMaxDynamicSharedMemorySize,
                         FLASH_SMEM_BYTES);
    cudaFuncSetAttribute(gemm_tf32, cudaFuncAttributeMaxDynamicSharedMemorySize,
                         GEMM_SMEM_BYTES);

    pad_kernel<<<1, 256>>>(ids);

    const int TOT4 = XN4 + 4 * WN4;
    round_all<<<TOT4 / 256, 256>>>((const float4*)x, (const float4*)Wq,
                                   (const float4*)Wk, (const float4*)Wv,
                                   (const float4*)Wo, (float4*)Xp, (float4*)WRp);

    dim3 gqkv(DM / 128, M_TOT / 128, 3);   // (8, 32, 3)
    gemm_tf32<<<gqkv, 256, GEMM_SMEM_BYTES>>>(Xp, WRp, bq, bk, bv, Qp, Kp, Vp, 1);

    dim3 gf(8, NH, BATCH);                 // paired q-tiles: 256 blocks
    flash_tc<<<gf, 256, FLASH_SMEM_BYTES>>>(Qp, Kp, Vp, Op);

    dim3 go(DM / 128, M_TOT / 128, 1);
    gemm_tf32<<<go, 256, GEMM_SMEM_BYTES>>>(Op, WRp + 3 * (size_t)DM * DM,
                                            bo, bo, bo, out, out, out, 0);
}